// round 5
// baseline (speedup 1.0000x reference)
#include <cuda_runtime.h>
#include <cstdint>

#define N_NODES 50000
#define N_EDGES 800000
#define D       128
#define SCAN_T  1024

// ---- scratch (device globals; no allocation allowed) ----
__device__ __align__(16) float g_z[(size_t)N_NODES * D];    // z = dinv * (x @ Wc)
__device__ __align__(16) float g_dinv[N_NODES];
__device__ int   g_deg[N_NODES];        // neighbor in-degree (no self loop)
__device__ int   g_off[N_NODES + 1];    // CSR offsets over dst
__device__ int   g_cursor[N_NODES];     // fill cursors
__device__ int   g_csr_src[N_EDGES];    // src node per CSR slot
__device__ __align__(16) float g_M1[D * D];   // I + Wt
__device__ __align__(16) float g_M2[D * D];   // W0 - Wt
__device__ int   g_is64;                // 1 if edge_index is int64, 0 if int32

// ---------------------------------------------------------------------------
// K-1: detect edge_index dtype. Indices are < 50000, so a genuine int64
// always has zero high word. For int32 data, the "high word" of a 64-bit
// read is the NEXT index — essentially never 0 across 4096 samples.
// ---------------------------------------------------------------------------
__global__ void k_detect(const long long* __restrict__ ei) {
    __shared__ int any_hi;
    if (threadIdx.x == 0) any_hi = 0;
    __syncthreads();
    int found = 0;
    for (int i = threadIdx.x; i < 4096; i += blockDim.x) {
        if ((unsigned long long)ei[i] >> 32) found = 1;
    }
    if (found) atomicOr(&any_hi, 1);
    __syncthreads();
    if (threadIdx.x == 0) g_is64 = any_hi ? 0 : 1;
}

__device__ __forceinline__ int edge_at(const void* ei, int use64, size_t idx) {
    return use64 ? (int)((const long long*)ei)[idx]
                 : ((const int*)ei)[idx];
}

// ---------------------------------------------------------------------------
// K0: deg=0, build combined weights M1/M2
// ---------------------------------------------------------------------------
__global__ void k_init(const float* __restrict__ W0, const float* __restrict__ Wt) {
    int tid = blockIdx.x * blockDim.x + threadIdx.x;
    int stride = gridDim.x * blockDim.x;
    for (int i = tid; i < N_NODES; i += stride) g_deg[i] = 0;
    for (int i = tid; i < D * D; i += stride) {
        int k = i / D, c = i % D;
        float wt = Wt[i];
        g_M1[i] = wt + (k == c ? 1.0f : 0.0f);
        g_M2[i] = W0[i] - wt;
    }
}

// ---------------------------------------------------------------------------
// K1: in-degree histogram over dst (int atomics; range-guarded)
// dst row starts at element offset N_EDGES regardless of dtype.
// ---------------------------------------------------------------------------
__global__ void k_degree(const void* __restrict__ ei) {
    int use64 = g_is64;
    int tid = blockIdx.x * blockDim.x + threadIdx.x;
    int stride = gridDim.x * blockDim.x;
    for (int e = tid; e < N_EDGES; e += stride) {
        unsigned d = (unsigned)edge_at(ei, use64, (size_t)N_EDGES + e);
        if (d < N_NODES) atomicAdd(&g_deg[d], 1);
    }
}

// ---------------------------------------------------------------------------
// K2: single-block exclusive scan of deg -> off; cursor = off; dinv = rsqrt(deg+1)
// ---------------------------------------------------------------------------
__global__ __launch_bounds__(SCAN_T) void k_scan() {
    __shared__ int partial[SCAN_T];
    int t = threadIdx.x;
    const int C = (N_NODES + SCAN_T - 1) / SCAN_T;   // 49
    int beg = t * C, end = min(beg + C, N_NODES);

    int s = 0;
    for (int i = beg; i < end; i++) s += g_deg[i];
    partial[t] = s;
    __syncthreads();

    for (int d = 1; d < SCAN_T; d <<= 1) {
        int v = (t >= d) ? partial[t - d] : 0;
        __syncthreads();
        partial[t] += v;
        __syncthreads();
    }
    int base = (t > 0) ? partial[t - 1] : 0;

    int run = base;
    for (int i = beg; i < end; i++) {
        int dg = g_deg[i];
        g_off[i] = run;
        g_cursor[i] = run;
        g_dinv[i] = rsqrtf((float)(dg + 1));   // +1 self loop
        run += dg;
    }
    if (t == SCAN_T - 1) g_off[N_NODES] = run;
}

// ---------------------------------------------------------------------------
// K3: fill CSR (int atomics on spread cursors; range-guarded)
// ---------------------------------------------------------------------------
__global__ void k_fill(const void* __restrict__ ei) {
    int use64 = g_is64;
    int tid = blockIdx.x * blockDim.x + threadIdx.x;
    int stride = gridDim.x * blockDim.x;
    for (int e = tid; e < N_EDGES; e += stride) {
        unsigned s = (unsigned)edge_at(ei, use64, e);
        unsigned d = (unsigned)edge_at(ei, use64, (size_t)N_EDGES + e);
        if (d < N_NODES && s < N_NODES) {
            int pos = atomicAdd(&g_cursor[d], 1);
            g_csr_src[pos] = (int)s;
        }
    }
}

// ---------------------------------------------------------------------------
// K4: z = dinv * (x @ Wc).  Warp-per-row; Wc resident in SMEM.
// ---------------------------------------------------------------------------
__global__ __launch_bounds__(512) void k_gemm1(const float* __restrict__ x,
                                               const float* __restrict__ Wc) {
    extern __shared__ float sm[];
    float* Ws = sm;                 // [128*128]
    float* xs = sm + D * D;         // [16 warps * 128]
    int tid = threadIdx.x, warp = tid >> 5, lane = tid & 31;

    for (int i = tid; i < D * D / 4; i += blockDim.x)
        ((float4*)Ws)[i] = ((const float4*)Wc)[i];
    __syncthreads();

    int nwarps = gridDim.x * (blockDim.x >> 5);
    float* xr = xs + warp * D;
    for (int row = blockIdx.x * (blockDim.x >> 5) + warp; row < N_NODES; row += nwarps) {
        size_t base = (size_t)row * D;
        ((float4*)xr)[lane] = ((const float4*)(x + base))[lane];
        __syncwarp();
        float4 acc = make_float4(0.f, 0.f, 0.f, 0.f);
#pragma unroll 16
        for (int k = 0; k < D; k++) {
            float xv = xr[k];
            float4 w = ((const float4*)(Ws + k * D))[lane];
            acc.x += xv * w.x; acc.y += xv * w.y;
            acc.z += xv * w.z; acc.w += xv * w.w;
        }
        float s = g_dinv[row];
        acc.x *= s; acc.y *= s; acc.z *= s; acc.w *= s;
        ((float4*)(g_z + base))[lane] = acc;
        __syncwarp();
    }
}

// ---------------------------------------------------------------------------
// K5 (fused): per row — CSR gather of z, fold self-loop+bias into h,
//             then out = h @ M1 + x @ M2.  Warp-per-row.
// ---------------------------------------------------------------------------
__global__ __launch_bounds__(512) void k_final(const float* __restrict__ x,
                                               const float* __restrict__ bc,
                                               float* __restrict__ out) {
    extern __shared__ float sm[];
    float* M1s = sm;                       // 16384
    float* M2s = sm + D * D;               // 16384
    float* bcs = sm + 2 * D * D;           // 128
    float* hst = bcs + D;                  // 16 warps * 128
    float* xst = hst + 16 * D;             // 16 warps * 128
    int tid = threadIdx.x, warp = tid >> 5, lane = tid & 31;

    for (int i = tid; i < D * D / 4; i += blockDim.x) {
        ((float4*)M1s)[i] = ((const float4*)g_M1)[i];
        ((float4*)M2s)[i] = ((const float4*)g_M2)[i];
    }
    if (tid < D) bcs[tid] = bc[tid];
    __syncthreads();

    int nwarps = gridDim.x * (blockDim.x >> 5);
    float* hr = hst + warp * D;
    float* xr = xst + warp * D;
    for (int row = blockIdx.x * (blockDim.x >> 5) + warp; row < N_NODES; row += nwarps) {
        size_t base = (size_t)row * D;

        // ---- CSR gather: acc = z[row] (self loop) + sum_{src->row} z[src]
        float4 acc = ((const float4*)(g_z + base))[lane];
        int e = g_off[row], end = g_off[row + 1];
        for (; e + 3 < end; e += 4) {
            int s0 = __ldg(&g_csr_src[e]);
            int s1 = __ldg(&g_csr_src[e + 1]);
            int s2 = __ldg(&g_csr_src[e + 2]);
            int s3 = __ldg(&g_csr_src[e + 3]);
            float4 v0 = ((const float4*)(g_z + (size_t)s0 * D))[lane];
            float4 v1 = ((const float4*)(g_z + (size_t)s1 * D))[lane];
            float4 v2 = ((const float4*)(g_z + (size_t)s2 * D))[lane];
            float4 v3 = ((const float4*)(g_z + (size_t)s3 * D))[lane];
            acc.x += v0.x + v1.x + v2.x + v3.x;
            acc.y += v0.y + v1.y + v2.y + v3.y;
            acc.z += v0.z + v1.z + v2.z + v3.z;
            acc.w += v0.w + v1.w + v2.w + v3.w;
        }
        for (; e < end; e++) {
            int s0 = __ldg(&g_csr_src[e]);
            float4 v0 = ((const float4*)(g_z + (size_t)s0 * D))[lane];
            acc.x += v0.x; acc.y += v0.y; acc.z += v0.z; acc.w += v0.w;
        }

        float s = g_dinv[row];
        float4 b4 = ((const float4*)bcs)[lane];
        float4 x4 = ((const float4*)(x + base))[lane];
        float4 h4;
        h4.x = s * acc.x + b4.x;
        h4.y = s * acc.y + b4.y;
        h4.z = s * acc.z + b4.z;
        h4.w = s * acc.w + b4.w;
        ((float4*)hr)[lane] = h4;
        ((float4*)xr)[lane] = x4;
        __syncwarp();

        // ---- dual GEMM epilogue
        float4 o = make_float4(0.f, 0.f, 0.f, 0.f);
#pragma unroll 16
        for (int k = 0; k < D; k++) {
            float hv = hr[k];
            float4 m1 = ((const float4*)(M1s + k * D))[lane];
            o.x += hv * m1.x; o.y += hv * m1.y;
            o.z += hv * m1.z; o.w += hv * m1.w;
            float xv = xr[k];
            float4 m2 = ((const float4*)(M2s + k * D))[lane];
            o.x += xv * m2.x; o.y += xv * m2.y;
            o.z += xv * m2.z; o.w += xv * m2.w;
        }
        ((float4*)(out + base))[lane] = o;
        __syncwarp();
    }
}

// ---------------------------------------------------------------------------
extern "C" void kernel_launch(void* const* d_in, const int* in_sizes, int n_in,
                              void* d_out, int out_size) {
    // Positional defaults per metadata order: x, edge_index, Wc, bc, W0, Wt.
    const float* x  = (const float*)d_in[0];
    const void*  ei = d_in[1];
    const float* Wc = (const float*)d_in[2];
    const float* bc = (const float*)d_in[3];
    const float* W0 = (const float*)d_in[4];
    const float* Wt = (const float*)d_in[5];

    // Size-based override where unambiguous (edge_index element count may be
    // reported as 1.6M (int64 or int32-pairs) or 3.2M (int32)).
    {
        const float* fx = nullptr; const void* fei = nullptr;
        const float* fbc = nullptr;
        const float* w[3] = {nullptr, nullptr, nullptr}; int nw = 0;
        for (int i = 0; i < n_in; i++) {
            int sz = in_sizes[i];
            if (sz == N_NODES * D)                           fx  = (const float*)d_in[i];
            else if (sz == 2 * N_EDGES || sz == 4 * N_EDGES) fei = d_in[i];
            else if (sz == D)                                fbc = (const float*)d_in[i];
            else if (sz == D * D && nw < 3)                  w[nw++] = (const float*)d_in[i];
        }
        if (fx)  x  = fx;
        if (fei) ei = fei;
        if (fbc) bc = fbc;
        if (nw == 3) { Wc = w[0]; W0 = w[1]; Wt = w[2]; }
    }
    float* out = (float*)d_out;

    int smem_gemm1 = (D * D + 16 * D) * (int)sizeof(float);               // 73,728 B
    int smem_final = (2 * D * D + D + 32 * D) * (int)sizeof(float);        // 147,968 B
    cudaFuncSetAttribute(k_gemm1, cudaFuncAttributeMaxDynamicSharedMemorySize, smem_gemm1);
    cudaFuncSetAttribute(k_final, cudaFuncAttributeMaxDynamicSharedMemorySize, smem_final);

    k_detect<<<1, 256>>>((const long long*)ei);
    k_init<<<512, 256>>>(W0, Wt);
    k_degree<<<1024, 256>>>(ei);
    k_scan<<<1, SCAN_T>>>();
    k_fill<<<1024, 256>>>(ei);
    k_gemm1<<<444, 512, smem_gemm1>>>(x, Wc);
    k_final<<<148, 512, smem_final>>>(x, bc, out);
}

// round 6
// speedup vs baseline: 1.2735x; 1.2735x over previous
#include <cuda_runtime.h>
#include <cstdint>

#define N_NODES 50000
#define N_EDGES 800000
#define D       128

#define SCAN_ITEMS 4
#define SCAN_BLK   256
#define SCAN_CHUNK (SCAN_BLK * SCAN_ITEMS)                       // 1024
#define SCAN_NBLK  ((N_NODES + SCAN_CHUNK - 1) / SCAN_CHUNK)     // 49

// ---- scratch (device globals; no allocation allowed) ----
__device__ __align__(16) float g_z[(size_t)N_NODES * D];    // z = dinv * (x @ Wc)
__device__ __align__(16) float g_dinv[N_NODES];
__device__ __align__(16) int   g_deg[N_NODES + 4];  // +pad so int4 reads stay in bounds
__device__ int   g_off[N_NODES + 1];    // CSR offsets over dst
__device__ int   g_cursor[N_NODES];     // fill cursors
__device__ int   g_csr_src[N_EDGES];    // src node per CSR slot
__device__ int   g_bsum[SCAN_NBLK];     // per-block deg sums
__device__ int   g_bbase[SCAN_NBLK];    // exclusive block bases
__device__ __align__(16) float g_M1[D * D];   // I + Wt
__device__ __align__(16) float g_M2[D * D];   // W0 - Wt
__device__ int   g_is64;                // 1 if edge_index is int64, 0 if int32

// ---------------------------------------------------------------------------
// K-1: detect edge_index dtype (indices < 50000 => int64 high words all zero)
// ---------------------------------------------------------------------------
__global__ void k_detect(const long long* __restrict__ ei) {
    __shared__ int any_hi;
    if (threadIdx.x == 0) any_hi = 0;
    __syncthreads();
    int found = 0;
    for (int i = threadIdx.x; i < 4096; i += blockDim.x) {
        if ((unsigned long long)ei[i] >> 32) found = 1;
    }
    if (found) atomicOr(&any_hi, 1);
    __syncthreads();
    if (threadIdx.x == 0) g_is64 = any_hi ? 0 : 1;
}

__device__ __forceinline__ int edge_at(const void* ei, int use64, size_t idx) {
    return use64 ? (int)((const long long*)ei)[idx]
                 : ((const int*)ei)[idx];
}

// ---------------------------------------------------------------------------
// K0: deg=0 (incl. pad), build combined weights M1/M2
// ---------------------------------------------------------------------------
__global__ void k_init(const float* __restrict__ W0, const float* __restrict__ Wt) {
    int tid = blockIdx.x * blockDim.x + threadIdx.x;
    int stride = gridDim.x * blockDim.x;
    for (int i = tid; i < N_NODES + 4; i += stride) g_deg[i] = 0;
    for (int i = tid; i < D * D; i += stride) {
        int k = i / D, c = i % D;
        float wt = Wt[i];
        g_M1[i] = wt + (k == c ? 1.0f : 0.0f);
        g_M2[i] = W0[i] - wt;
    }
}

// ---------------------------------------------------------------------------
// K1: in-degree histogram over dst (int atomics; range-guarded)
// ---------------------------------------------------------------------------
__global__ void k_degree(const void* __restrict__ ei) {
    int use64 = g_is64;
    int tid = blockIdx.x * blockDim.x + threadIdx.x;
    int stride = gridDim.x * blockDim.x;
    for (int e = tid; e < N_EDGES; e += stride) {
        unsigned d = (unsigned)edge_at(ei, use64, (size_t)N_EDGES + e);
        if (d < N_NODES) atomicAdd(&g_deg[d], 1);
    }
}

// ---------------------------------------------------------------------------
// K2a: per-block reduce of deg (int4 coalesced) -> g_bsum
// ---------------------------------------------------------------------------
__global__ __launch_bounds__(SCAN_BLK) void k_scanA() {
    __shared__ int warpsum[SCAN_BLK / 32];
    int t = threadIdx.x, b = blockIdx.x;
    int idx = b * SCAN_CHUNK + t * SCAN_ITEMS;
    int4 v = (idx < N_NODES + 4) ? ((const int4*)g_deg)[idx >> 2]
                                 : make_int4(0, 0, 0, 0);
    // zero any lanes past N_NODES (pad already zero, but be explicit)
    int s = 0;
    if (idx + 0 < N_NODES) s += v.x;
    if (idx + 1 < N_NODES) s += v.y;
    if (idx + 2 < N_NODES) s += v.z;
    if (idx + 3 < N_NODES) s += v.w;
#pragma unroll
    for (int o = 16; o > 0; o >>= 1) s += __shfl_down_sync(0xffffffffu, s, o);
    if ((t & 31) == 0) warpsum[t >> 5] = s;
    __syncthreads();
    if (t < SCAN_BLK / 32) {
        int ws = warpsum[t];
#pragma unroll
        for (int o = SCAN_BLK / 64; o > 0; o >>= 1)
            ws += __shfl_down_sync(0xffffffffu, ws, o);
        if (t == 0) g_bsum[b] = ws;
    }
}

// ---------------------------------------------------------------------------
// K2b: scan 49 block sums -> exclusive bases; write total
// ---------------------------------------------------------------------------
__global__ void k_scanB() {
    __shared__ int sh[64];
    int t = threadIdx.x;                  // 64 threads
    int v = (t < SCAN_NBLK) ? g_bsum[t] : 0;
    sh[t] = v;
    __syncthreads();
#pragma unroll
    for (int d = 1; d < 64; d <<= 1) {
        int u = (t >= d) ? sh[t - d] : 0;
        __syncthreads();
        sh[t] += u;
        __syncthreads();
    }
    if (t < SCAN_NBLK) g_bbase[t] = (t > 0) ? sh[t - 1] : 0;
    if (t == 63) g_off[N_NODES] = sh[SCAN_NBLK - 1];
}

// ---------------------------------------------------------------------------
// K2c: per-block local scan + base -> off, cursor, dinv (coalesced)
// ---------------------------------------------------------------------------
__global__ __launch_bounds__(SCAN_BLK) void k_scanC() {
    __shared__ int sh[SCAN_BLK];
    int t = threadIdx.x, b = blockIdx.x;
    int idx = b * SCAN_CHUNK + t * SCAN_ITEMS;
    int4 v = (idx < N_NODES + 4) ? ((const int4*)g_deg)[idx >> 2]
                                 : make_int4(0, 0, 0, 0);
    int d0 = (idx + 0 < N_NODES) ? v.x : 0;
    int d1 = (idx + 1 < N_NODES) ? v.y : 0;
    int d2 = (idx + 2 < N_NODES) ? v.z : 0;
    int d3 = (idx + 3 < N_NODES) ? v.w : 0;
    int s = d0 + d1 + d2 + d3;
    sh[t] = s;
    __syncthreads();
#pragma unroll
    for (int d = 1; d < SCAN_BLK; d <<= 1) {
        int u = (t >= d) ? sh[t - d] : 0;
        __syncthreads();
        sh[t] += u;
        __syncthreads();
    }
    int run = g_bbase[b] + ((t > 0) ? sh[t - 1] : 0);
    int dg[4] = {d0, d1, d2, d3};
#pragma unroll
    for (int j = 0; j < 4; j++) {
        int i = idx + j;
        if (i < N_NODES) {
            g_off[i] = run;
            g_cursor[i] = run;
            g_dinv[i] = rsqrtf((float)(dg[j] + 1));   // +1 self loop
            run += dg[j];
        }
    }
}

// ---------------------------------------------------------------------------
// K3: fill CSR (int atomics on spread cursors; range-guarded)
// ---------------------------------------------------------------------------
__global__ void k_fill(const void* __restrict__ ei) {
    int use64 = g_is64;
    int tid = blockIdx.x * blockDim.x + threadIdx.x;
    int stride = gridDim.x * blockDim.x;
    for (int e = tid; e < N_EDGES; e += stride) {
        unsigned s = (unsigned)edge_at(ei, use64, e);
        unsigned d = (unsigned)edge_at(ei, use64, (size_t)N_EDGES + e);
        if (d < N_NODES && s < N_NODES) {
            int pos = atomicAdd(&g_cursor[d], 1);
            g_csr_src[pos] = (int)s;
        }
    }
}

// ---------------------------------------------------------------------------
// K4: z = dinv * (x @ Wc).  Warp-per-row; Wc resident in SMEM.
// ---------------------------------------------------------------------------
__global__ __launch_bounds__(512) void k_gemm1(const float* __restrict__ x,
                                               const float* __restrict__ Wc) {
    extern __shared__ float sm[];
    float* Ws = sm;                 // [128*128]
    float* xs = sm + D * D;         // [16 warps * 128]
    int tid = threadIdx.x, warp = tid >> 5, lane = tid & 31;

    for (int i = tid; i < D * D / 4; i += blockDim.x)
        ((float4*)Ws)[i] = ((const float4*)Wc)[i];
    __syncthreads();

    int nwarps = gridDim.x * (blockDim.x >> 5);
    float* xr = xs + warp * D;
    for (int row = blockIdx.x * (blockDim.x >> 5) + warp; row < N_NODES; row += nwarps) {
        size_t base = (size_t)row * D;
        ((float4*)xr)[lane] = ((const float4*)(x + base))[lane];
        __syncwarp();
        float4 acc = make_float4(0.f, 0.f, 0.f, 0.f);
#pragma unroll 16
        for (int k = 0; k < D; k++) {
            float xv = xr[k];
            float4 w = ((const float4*)(Ws + k * D))[lane];
            acc.x += xv * w.x; acc.y += xv * w.y;
            acc.z += xv * w.z; acc.w += xv * w.w;
        }
        float s = g_dinv[row];
        acc.x *= s; acc.y *= s; acc.z *= s; acc.w *= s;
        ((float4*)(g_z + base))[lane] = acc;
        __syncwarp();
    }
}

// ---------------------------------------------------------------------------
// K5 (fused): per row — CSR gather of z (8-wide MLP), fold self-loop+bias,
//             then out = h @ M1 + x @ M2.  Warp-per-row.
// ---------------------------------------------------------------------------
__global__ __launch_bounds__(512) void k_final(const float* __restrict__ x,
                                               const float* __restrict__ bc,
                                               float* __restrict__ out) {
    extern __shared__ float sm[];
    float* M1s = sm;                       // 16384
    float* M2s = sm + D * D;               // 16384
    float* bcs = sm + 2 * D * D;           // 128
    float* hst = bcs + D;                  // 16 warps * 128
    float* xst = hst + 16 * D;             // 16 warps * 128
    int tid = threadIdx.x, warp = tid >> 5, lane = tid & 31;

    for (int i = tid; i < D * D / 4; i += blockDim.x) {
        ((float4*)M1s)[i] = ((const float4*)g_M1)[i];
        ((float4*)M2s)[i] = ((const float4*)g_M2)[i];
    }
    if (tid < D) bcs[tid] = bc[tid];
    __syncthreads();

    int nwarps = gridDim.x * (blockDim.x >> 5);
    float* hr = hst + warp * D;
    float* xr = xst + warp * D;
    for (int row = blockIdx.x * (blockDim.x >> 5) + warp; row < N_NODES; row += nwarps) {
        size_t base = (size_t)row * D;

        // ---- CSR gather: acc = z[row] (self loop) + sum_{src->row} z[src]
        float4 acc = ((const float4*)(g_z + base))[lane];
        int e = g_off[row], end = g_off[row + 1];
        for (; e + 7 < end; e += 8) {
            int s0 = __ldg(&g_csr_src[e]);
            int s1 = __ldg(&g_csr_src[e + 1]);
            int s2 = __ldg(&g_csr_src[e + 2]);
            int s3 = __ldg(&g_csr_src[e + 3]);
            int s4 = __ldg(&g_csr_src[e + 4]);
            int s5 = __ldg(&g_csr_src[e + 5]);
            int s6 = __ldg(&g_csr_src[e + 6]);
            int s7 = __ldg(&g_csr_src[e + 7]);
            float4 v0 = ((const float4*)(g_z + (size_t)s0 * D))[lane];
            float4 v1 = ((const float4*)(g_z + (size_t)s1 * D))[lane];
            float4 v2 = ((const float4*)(g_z + (size_t)s2 * D))[lane];
            float4 v3 = ((const float4*)(g_z + (size_t)s3 * D))[lane];
            float4 v4 = ((const float4*)(g_z + (size_t)s4 * D))[lane];
            float4 v5 = ((const float4*)(g_z + (size_t)s5 * D))[lane];
            float4 v6 = ((const float4*)(g_z + (size_t)s6 * D))[lane];
            float4 v7 = ((const float4*)(g_z + (size_t)s7 * D))[lane];
            acc.x += ((v0.x + v1.x) + (v2.x + v3.x)) + ((v4.x + v5.x) + (v6.x + v7.x));
            acc.y += ((v0.y + v1.y) + (v2.y + v3.y)) + ((v4.y + v5.y) + (v6.y + v7.y));
            acc.z += ((v0.z + v1.z) + (v2.z + v3.z)) + ((v4.z + v5.z) + (v6.z + v7.z));
            acc.w += ((v0.w + v1.w) + (v2.w + v3.w)) + ((v4.w + v5.w) + (v6.w + v7.w));
        }
        for (; e < end; e++) {
            int s0 = __ldg(&g_csr_src[e]);
            float4 v0 = ((const float4*)(g_z + (size_t)s0 * D))[lane];
            acc.x += v0.x; acc.y += v0.y; acc.z += v0.z; acc.w += v0.w;
        }

        float s = g_dinv[row];
        float4 b4 = ((const float4*)bcs)[lane];
        float4 x4 = ((const float4*)(x + base))[lane];
        float4 h4;
        h4.x = s * acc.x + b4.x;
        h4.y = s * acc.y + b4.y;
        h4.z = s * acc.z + b4.z;
        h4.w = s * acc.w + b4.w;
        ((float4*)hr)[lane] = h4;
        ((float4*)xr)[lane] = x4;
        __syncwarp();

        // ---- dual GEMM epilogue
        float4 o = make_float4(0.f, 0.f, 0.f, 0.f);
#pragma unroll 16
        for (int k = 0; k < D; k++) {
            float hv = hr[k];
            float4 m1 = ((const float4*)(M1s + k * D))[lane];
            o.x += hv * m1.x; o.y += hv * m1.y;
            o.z += hv * m1.z; o.w += hv * m1.w;
            float xv = xr[k];
            float4 m2 = ((const float4*)(M2s + k * D))[lane];
            o.x += xv * m2.x; o.y += xv * m2.y;
            o.z += xv * m2.z; o.w += xv * m2.w;
        }
        ((float4*)(out + base))[lane] = o;
        __syncwarp();
    }
}

// ---------------------------------------------------------------------------
extern "C" void kernel_launch(void* const* d_in, const int* in_sizes, int n_in,
                              void* d_out, int out_size) {
    // Positional defaults per metadata order: x, edge_index, Wc, bc, W0, Wt.
    const float* x  = (const float*)d_in[0];
    const void*  ei = d_in[1];
    const float* Wc = (const float*)d_in[2];
    const float* bc = (const float*)d_in[3];
    const float* W0 = (const float*)d_in[4];
    const float* Wt = (const float*)d_in[5];

    // Size-based override where unambiguous.
    {
        const float* fx = nullptr; const void* fei = nullptr;
        const float* fbc = nullptr;
        const float* w[3] = {nullptr, nullptr, nullptr}; int nw = 0;
        for (int i = 0; i < n_in; i++) {
            int sz = in_sizes[i];
            if (sz == N_NODES * D)                           fx  = (const float*)d_in[i];
            else if (sz == 2 * N_EDGES || sz == 4 * N_EDGES) fei = d_in[i];
            else if (sz == D)                                fbc = (const float*)d_in[i];
            else if (sz == D * D && nw < 3)                  w[nw++] = (const float*)d_in[i];
        }
        if (fx)  x  = fx;
        if (fei) ei = fei;
        if (fbc) bc = fbc;
        if (nw == 3) { Wc = w[0]; W0 = w[1]; Wt = w[2]; }
    }
    float* out = (float*)d_out;

    int smem_gemm1 = (D * D + 16 * D) * (int)sizeof(float);               // 73,728 B
    int smem_final = (2 * D * D + D + 32 * D) * (int)sizeof(float);        // 147,968 B
    cudaFuncSetAttribute(k_gemm1, cudaFuncAttributeMaxDynamicSharedMemorySize, smem_gemm1);
    cudaFuncSetAttribute(k_final, cudaFuncAttributeMaxDynamicSharedMemorySize, smem_final);

    k_detect<<<1, 256>>>((const long long*)ei);
    k_init<<<512, 256>>>(W0, Wt);
    k_degree<<<1024, 256>>>(ei);
    k_scanA<<<SCAN_NBLK, SCAN_BLK>>>();
    k_scanB<<<1, 64>>>();
    k_scanC<<<SCAN_NBLK, SCAN_BLK>>>();
    k_fill<<<1024, 256>>>(ei);
    k_gemm1<<<444, 512, smem_gemm1>>>(x, Wc);
    k_final<<<148, 512, smem_final>>>(x, bc, out);
}

// round 7
// speedup vs baseline: 1.7383x; 1.3650x over previous
#include <cuda_runtime.h>
#include <cstdint>

#define N_NODES 50000
#define N_EDGES 800000
#define D       128
#define RT      8                      // rows per warp tile

#define SCAN_ITEMS 4
#define SCAN_BLK   256
#define SCAN_CHUNK (SCAN_BLK * SCAN_ITEMS)                       // 1024
#define SCAN_NBLK  ((N_NODES + SCAN_CHUNK - 1) / SCAN_CHUNK)     // 49

// ---- scratch (device globals; no allocation allowed) ----
__device__ __align__(16) float g_z[(size_t)N_NODES * D];    // z = dinv * (x @ Wc)
__device__ __align__(16) float g_dinv[N_NODES];
__device__ __align__(16) int   g_deg[N_NODES + 4];
__device__ int   g_off[N_NODES + 1];
__device__ int   g_cursor[N_NODES];
__device__ int   g_csr_src[N_EDGES];
__device__ int   g_bsum[SCAN_NBLK];
__device__ int   g_bbase[SCAN_NBLK];
__device__ int   g_is64;

// ---------------------------------------------------------------------------
__global__ void k_detect(const long long* __restrict__ ei) {
    __shared__ int any_hi;
    if (threadIdx.x == 0) any_hi = 0;
    __syncthreads();
    int found = 0;
    for (int i = threadIdx.x; i < 4096; i += blockDim.x) {
        if ((unsigned long long)ei[i] >> 32) found = 1;
    }
    if (found) atomicOr(&any_hi, 1);
    __syncthreads();
    if (threadIdx.x == 0) g_is64 = any_hi ? 0 : 1;
}

__device__ __forceinline__ int edge_at(const void* ei, int use64, size_t idx) {
    return use64 ? (int)((const long long*)ei)[idx]
                 : ((const int*)ei)[idx];
}

// ---------------------------------------------------------------------------
__global__ void k_init() {
    int tid = blockIdx.x * blockDim.x + threadIdx.x;
    int stride = gridDim.x * blockDim.x;
    for (int i = tid; i < N_NODES + 4; i += stride) g_deg[i] = 0;
}

// ---------------------------------------------------------------------------
__global__ void k_degree(const void* __restrict__ ei) {
    int use64 = g_is64;
    int tid = blockIdx.x * blockDim.x + threadIdx.x;
    int stride = gridDim.x * blockDim.x;
    for (int e = tid; e < N_EDGES; e += stride) {
        unsigned d = (unsigned)edge_at(ei, use64, (size_t)N_EDGES + e);
        if (d < N_NODES) atomicAdd(&g_deg[d], 1);
    }
}

// ---------------------------------------------------------------------------
__global__ __launch_bounds__(SCAN_BLK) void k_scanA() {
    __shared__ int warpsum[SCAN_BLK / 32];
    int t = threadIdx.x, b = blockIdx.x;
    int idx = b * SCAN_CHUNK + t * SCAN_ITEMS;
    int4 v = (idx < N_NODES + 4) ? ((const int4*)g_deg)[idx >> 2]
                                 : make_int4(0, 0, 0, 0);
    int s = 0;
    if (idx + 0 < N_NODES) s += v.x;
    if (idx + 1 < N_NODES) s += v.y;
    if (idx + 2 < N_NODES) s += v.z;
    if (idx + 3 < N_NODES) s += v.w;
#pragma unroll
    for (int o = 16; o > 0; o >>= 1) s += __shfl_down_sync(0xffffffffu, s, o);
    if ((t & 31) == 0) warpsum[t >> 5] = s;
    __syncthreads();
    if (t < SCAN_BLK / 32) {
        int ws = warpsum[t];
#pragma unroll
        for (int o = SCAN_BLK / 64; o > 0; o >>= 1)
            ws += __shfl_down_sync(0xffffffffu, ws, o);
        if (t == 0) g_bsum[b] = ws;
    }
}

__global__ void k_scanB() {
    __shared__ int sh[64];
    int t = threadIdx.x;
    int v = (t < SCAN_NBLK) ? g_bsum[t] : 0;
    sh[t] = v;
    __syncthreads();
#pragma unroll
    for (int d = 1; d < 64; d <<= 1) {
        int u = (t >= d) ? sh[t - d] : 0;
        __syncthreads();
        sh[t] += u;
        __syncthreads();
    }
    if (t < SCAN_NBLK) g_bbase[t] = (t > 0) ? sh[t - 1] : 0;
    if (t == 63) g_off[N_NODES] = sh[SCAN_NBLK - 1];
}

__global__ __launch_bounds__(SCAN_BLK) void k_scanC() {
    __shared__ int sh[SCAN_BLK];
    int t = threadIdx.x, b = blockIdx.x;
    int idx = b * SCAN_CHUNK + t * SCAN_ITEMS;
    int4 v = (idx < N_NODES + 4) ? ((const int4*)g_deg)[idx >> 2]
                                 : make_int4(0, 0, 0, 0);
    int d0 = (idx + 0 < N_NODES) ? v.x : 0;
    int d1 = (idx + 1 < N_NODES) ? v.y : 0;
    int d2 = (idx + 2 < N_NODES) ? v.z : 0;
    int d3 = (idx + 3 < N_NODES) ? v.w : 0;
    sh[t] = d0 + d1 + d2 + d3;
    __syncthreads();
#pragma unroll
    for (int d = 1; d < SCAN_BLK; d <<= 1) {
        int u = (t >= d) ? sh[t - d] : 0;
        __syncthreads();
        sh[t] += u;
        __syncthreads();
    }
    int run = g_bbase[b] + ((t > 0) ? sh[t - 1] : 0);
    int dg[4] = {d0, d1, d2, d3};
#pragma unroll
    for (int j = 0; j < 4; j++) {
        int i = idx + j;
        if (i < N_NODES) {
            g_off[i] = run;
            g_cursor[i] = run;
            g_dinv[i] = rsqrtf((float)(dg[j] + 1));
            run += dg[j];
        }
    }
}

// ---------------------------------------------------------------------------
__global__ void k_fill(const void* __restrict__ ei) {
    int use64 = g_is64;
    int tid = blockIdx.x * blockDim.x + threadIdx.x;
    int stride = gridDim.x * blockDim.x;
    for (int e = tid; e < N_EDGES; e += stride) {
        unsigned s = (unsigned)edge_at(ei, use64, e);
        unsigned d = (unsigned)edge_at(ei, use64, (size_t)N_EDGES + e);
        if (d < N_NODES && s < N_NODES) {
            int pos = atomicAdd(&g_cursor[d], 1);
            g_csr_src[pos] = (int)s;
        }
    }
}

// ---------------------------------------------------------------------------
// K4: z = dinv * (x @ Wc).  8-row warp tiles: one weight LDS.128 amortized
// over 8 rows -> FMA-bound instead of smem-crossbar-bound.
// ---------------------------------------------------------------------------
__global__ __launch_bounds__(256) void k_gemm1(const float* __restrict__ x,
                                               const float* __restrict__ Wc) {
    extern __shared__ float sm[];
    float* Ws = sm;                          // 16384 floats (64 KB)
    float* xt = sm + D * D;                  // 8 warps * 8 rows * 128
    int tid = threadIdx.x, warp = tid >> 5, lane = tid & 31;

    for (int i = tid; i < D * D / 4; i += 256)
        ((float4*)Ws)[i] = ((const float4*)Wc)[i];
    __syncthreads();

    float* xw = xt + warp * (RT * D);
    const int ngroups = (N_NODES + RT - 1) / RT;
    const int wstride = gridDim.x * 8;
    for (int g = blockIdx.x * 8 + warp; g < ngroups; g += wstride) {
        int row0 = g * RT;
#pragma unroll
        for (int r = 0; r < RT; r++) {
            int row = row0 + r;
            float4 v = (row < N_NODES) ? ((const float4*)(x + (size_t)row * D))[lane]
                                       : make_float4(0.f, 0.f, 0.f, 0.f);
            ((float4*)(xw + r * D))[lane] = v;
        }
        __syncwarp();
        float4 acc[RT];
#pragma unroll
        for (int r = 0; r < RT; r++) acc[r] = make_float4(0.f, 0.f, 0.f, 0.f);
#pragma unroll 4
        for (int k = 0; k < D; k++) {
            float4 w = ((const float4*)(Ws + k * D))[lane];
#pragma unroll
            for (int r = 0; r < RT; r++) {
                float xv = xw[r * D + k];
                acc[r].x += xv * w.x; acc[r].y += xv * w.y;
                acc[r].z += xv * w.z; acc[r].w += xv * w.w;
            }
        }
#pragma unroll
        for (int r = 0; r < RT; r++) {
            int row = row0 + r;
            if (row < N_NODES) {
                float s = g_dinv[row];
                float4 a = acc[r];
                a.x *= s; a.y *= s; a.z *= s; a.w *= s;
                ((float4*)(g_z + (size_t)row * D))[lane] = a;
            }
        }
        __syncwarp();
    }
}

// ---------------------------------------------------------------------------
// K5 (fused): per 8-row warp tile — CSR gather of z, fold self-loop+bias,
//             then out = h @ (I+Wt) + x @ (W0-Wt), weights built in smem.
// ---------------------------------------------------------------------------
__global__ __launch_bounds__(256) void k_final(const float* __restrict__ x,
                                               const float* __restrict__ bc,
                                               const float* __restrict__ W0,
                                               const float* __restrict__ Wt,
                                               float* __restrict__ out) {
    extern __shared__ float sm[];
    float* M1s = sm;                         // 16384
    float* M2s = sm + D * D;                 // 16384
    float* bcs = sm + 2 * D * D;             // 128
    float* tiles = bcs + D;                  // 8 warps * (2 * 8 * 128)
    int tid = threadIdx.x, warp = tid >> 5, lane = tid & 31;

    // Build M1 = Wt + I, M2 = W0 - Wt directly in smem.
    for (int i = tid; i < D * D / 4; i += 256) {
        float4 wt = ((const float4*)Wt)[i];
        float4 w0 = ((const float4*)W0)[i];
        int r = (i * 4) / D, c0 = (i * 4) % D;
        float m1v[4] = {wt.x, wt.y, wt.z, wt.w};
        int dd = r - c0;
        if (dd >= 0 && dd < 4) m1v[dd] += 1.0f;
        ((float4*)M1s)[i] = make_float4(m1v[0], m1v[1], m1v[2], m1v[3]);
        ((float4*)M2s)[i] = make_float4(w0.x - wt.x, w0.y - wt.y,
                                        w0.z - wt.z, w0.w - wt.w);
    }
    if (tid < D) bcs[tid] = bc[tid];
    __syncthreads();

    float* ht = tiles + warp * (2 * RT * D);
    float* xt = ht + RT * D;

    const int ngroups = (N_NODES + RT - 1) / RT;
    const int wstride = gridDim.x * 8;
    for (int g = blockIdx.x * 8 + warp; g < ngroups; g += wstride) {
        int row0 = g * RT;

        // ---- gather phase: h[r] = dinv*(z[row] + sum z[src]) + bc
#pragma unroll
        for (int r = 0; r < RT; r++) {
            int row = row0 + r;
            if (row >= N_NODES) {
                ((float4*)(ht + r * D))[lane] = make_float4(0.f, 0.f, 0.f, 0.f);
                ((float4*)(xt + r * D))[lane] = make_float4(0.f, 0.f, 0.f, 0.f);
                continue;
            }
            size_t base = (size_t)row * D;
            float4 acc = ((const float4*)(g_z + base))[lane];
            int e = g_off[row], end = g_off[row + 1];
            for (; e + 7 < end; e += 8) {
                int s0 = __ldg(&g_csr_src[e]);
                int s1 = __ldg(&g_csr_src[e + 1]);
                int s2 = __ldg(&g_csr_src[e + 2]);
                int s3 = __ldg(&g_csr_src[e + 3]);
                int s4 = __ldg(&g_csr_src[e + 4]);
                int s5 = __ldg(&g_csr_src[e + 5]);
                int s6 = __ldg(&g_csr_src[e + 6]);
                int s7 = __ldg(&g_csr_src[e + 7]);
                float4 v0 = ((const float4*)(g_z + (size_t)s0 * D))[lane];
                float4 v1 = ((const float4*)(g_z + (size_t)s1 * D))[lane];
                float4 v2 = ((const float4*)(g_z + (size_t)s2 * D))[lane];
                float4 v3 = ((const float4*)(g_z + (size_t)s3 * D))[lane];
                float4 v4 = ((const float4*)(g_z + (size_t)s4 * D))[lane];
                float4 v5 = ((const float4*)(g_z + (size_t)s5 * D))[lane];
                float4 v6 = ((const float4*)(g_z + (size_t)s6 * D))[lane];
                float4 v7 = ((const float4*)(g_z + (size_t)s7 * D))[lane];
                acc.x += ((v0.x + v1.x) + (v2.x + v3.x)) + ((v4.x + v5.x) + (v6.x + v7.x));
                acc.y += ((v0.y + v1.y) + (v2.y + v3.y)) + ((v4.y + v5.y) + (v6.y + v7.y));
                acc.z += ((v0.z + v1.z) + (v2.z + v3.z)) + ((v4.z + v5.z) + (v6.z + v7.z));
                acc.w += ((v0.w + v1.w) + (v2.w + v3.w)) + ((v4.w + v5.w) + (v6.w + v7.w));
            }
            for (; e < end; e++) {
                int s0 = __ldg(&g_csr_src[e]);
                float4 v0 = ((const float4*)(g_z + (size_t)s0 * D))[lane];
                acc.x += v0.x; acc.y += v0.y; acc.z += v0.z; acc.w += v0.w;
            }
            float s = g_dinv[row];
            float4 b4 = ((const float4*)bcs)[lane];
            float4 x4 = ((const float4*)(x + base))[lane];
            float4 h4;
            h4.x = s * acc.x + b4.x;
            h4.y = s * acc.y + b4.y;
            h4.z = s * acc.z + b4.z;
            h4.w = s * acc.w + b4.w;
            ((float4*)(ht + r * D))[lane] = h4;
            ((float4*)(xt + r * D))[lane] = x4;
        }
        __syncwarp();

        // ---- dual GEMM: o[r] = h[r] @ M1 + x[r] @ M2
        float4 o[RT];
#pragma unroll
        for (int r = 0; r < RT; r++) o[r] = make_float4(0.f, 0.f, 0.f, 0.f);
#pragma unroll 2
        for (int k = 0; k < D; k++) {
            float4 m1 = ((const float4*)(M1s + k * D))[lane];
            float4 m2 = ((const float4*)(M2s + k * D))[lane];
#pragma unroll
            for (int r = 0; r < RT; r++) {
                float hv = ht[r * D + k];
                float xv = xt[r * D + k];
                o[r].x += hv * m1.x + xv * m2.x;
                o[r].y += hv * m1.y + xv * m2.y;
                o[r].z += hv * m1.z + xv * m2.z;
                o[r].w += hv * m1.w + xv * m2.w;
            }
        }
#pragma unroll
        for (int r = 0; r < RT; r++) {
            int row = row0 + r;
            if (row < N_NODES)
                ((float4*)(out + (size_t)row * D))[lane] = o[r];
        }
        __syncwarp();
    }
}

// ---------------------------------------------------------------------------
extern "C" void kernel_launch(void* const* d_in, const int* in_sizes, int n_in,
                              void* d_out, int out_size) {
    const float* x  = (const float*)d_in[0];
    const void*  ei = d_in[1];
    const float* Wc = (const float*)d_in[2];
    const float* bc = (const float*)d_in[3];
    const float* W0 = (const float*)d_in[4];
    const float* Wt = (const float*)d_in[5];

    {
        const float* fx = nullptr; const void* fei = nullptr;
        const float* fbc = nullptr;
        const float* w[3] = {nullptr, nullptr, nullptr}; int nw = 0;
        for (int i = 0; i < n_in; i++) {
            int sz = in_sizes[i];
            if (sz == N_NODES * D)                           fx  = (const float*)d_in[i];
            else if (sz == 2 * N_EDGES || sz == 4 * N_EDGES) fei = d_in[i];
            else if (sz == D)                                fbc = (const float*)d_in[i];
            else if (sz == D * D && nw < 3)                  w[nw++] = (const float*)d_in[i];
        }
        if (fx)  x  = fx;
        if (fei) ei = fei;
        if (fbc) bc = fbc;
        if (nw == 3) { Wc = w[0]; W0 = w[1]; Wt = w[2]; }
    }
    float* out = (float*)d_out;

    int smem_gemm1 = (D * D + 8 * RT * D) * (int)sizeof(float);                // 98,304 B
    int smem_final = (2 * D * D + D + 8 * 2 * RT * D) * (int)sizeof(float);    // 197,120 B
    cudaFuncSetAttribute(k_gemm1, cudaFuncAttributeMaxDynamicSharedMemorySize, smem_gemm1);
    cudaFuncSetAttribute(k_final, cudaFuncAttributeMaxDynamicSharedMemorySize, smem_final);

    k_detect<<<1, 256>>>((const long long*)ei);
    k_init<<<256, 256>>>();
    k_degree<<<1024, 256>>>(ei);
    k_scanA<<<SCAN_NBLK, SCAN_BLK>>>();
    k_scanB<<<1, 64>>>();
    k_scanC<<<SCAN_NBLK, SCAN_BLK>>>();
    k_fill<<<1024, 256>>>(ei);
    k_gemm1<<<296, 256, smem_gemm1>>>(x, Wc);
    k_final<<<148, 256, smem_final>>>(x, bc, W0, Wt, out);
}

// round 8
// speedup vs baseline: 1.9617x; 1.1285x over previous
#include <cuda_runtime.h>
#include <cstdint>

#define N_NODES 50000
#define N_EDGES 800000
#define D       128
#define RT      8                      // rows per warp tile

#define SCAN_ITEMS 4
#define SCAN_BLK   256
#define SCAN_CHUNK (SCAN_BLK * SCAN_ITEMS)                       // 1024
#define SCAN_NBLK  ((N_NODES + SCAN_CHUNK - 1) / SCAN_CHUNK)     // 49

// ---- packed f32x2 helpers (FFMA2: 2 fp32 FMAs per issue slot) ----
#define FMA_X2(acc, a, b) \
    asm("fma.rn.f32x2 %0, %1, %2, %0;" : "+l"(acc) : "l"(a), "l"(b))
#define MUL_X2(out, a, b) \
    asm("mul.rn.f32x2 %0, %1, %2;" : "=l"(out) : "l"(a), "l"(b))
#define PACK_DUP(out, xi) \
    asm("mov.b64 %0, {%1, %1};" : "=l"(out) : "r"(xi))

// ---- scratch (device globals; no allocation allowed) ----
__device__ __align__(16) float g_z[(size_t)N_NODES * D];    // z = dinv * (x @ Wc)
__device__ __align__(16) float g_dinv[N_NODES];
__device__ __align__(16) int   g_deg[N_NODES + 4];
__device__ int   g_off[N_NODES + 1];
__device__ int   g_cursor[N_NODES];
__device__ int   g_csr_src[N_EDGES];
__device__ int   g_bsum[SCAN_NBLK];
__device__ int   g_bbase[SCAN_NBLK];
__device__ int   g_is64;

// ---------------------------------------------------------------------------
__global__ void k_detect(const long long* __restrict__ ei) {
    __shared__ int any_hi;
    if (threadIdx.x == 0) any_hi = 0;
    __syncthreads();
    int found = 0;
    for (int i = threadIdx.x; i < 4096; i += blockDim.x) {
        if ((unsigned long long)ei[i] >> 32) found = 1;
    }
    if (found) atomicOr(&any_hi, 1);
    __syncthreads();
    if (threadIdx.x == 0) g_is64 = any_hi ? 0 : 1;
}

__device__ __forceinline__ int edge_at(const void* ei, int use64, size_t idx) {
    return use64 ? (int)((const long long*)ei)[idx]
                 : ((const int*)ei)[idx];
}

// ---------------------------------------------------------------------------
__global__ void k_init() {
    int tid = blockIdx.x * blockDim.x + threadIdx.x;
    int stride = gridDim.x * blockDim.x;
    for (int i = tid; i < N_NODES + 4; i += stride) g_deg[i] = 0;
}

// ---------------------------------------------------------------------------
__global__ void k_degree(const void* __restrict__ ei) {
    int use64 = g_is64;
    int tid = blockIdx.x * blockDim.x + threadIdx.x;
    int stride = gridDim.x * blockDim.x;
    for (int e = tid; e < N_EDGES; e += stride) {
        unsigned d = (unsigned)edge_at(ei, use64, (size_t)N_EDGES + e);
        if (d < N_NODES) atomicAdd(&g_deg[d], 1);
    }
}

// ---------------------------------------------------------------------------
__global__ __launch_bounds__(SCAN_BLK) void k_scanA() {
    __shared__ int warpsum[SCAN_BLK / 32];
    int t = threadIdx.x, b = blockIdx.x;
    int idx = b * SCAN_CHUNK + t * SCAN_ITEMS;
    int4 v = (idx < N_NODES + 4) ? ((const int4*)g_deg)[idx >> 2]
                                 : make_int4(0, 0, 0, 0);
    int s = 0;
    if (idx + 0 < N_NODES) s += v.x;
    if (idx + 1 < N_NODES) s += v.y;
    if (idx + 2 < N_NODES) s += v.z;
    if (idx + 3 < N_NODES) s += v.w;
#pragma unroll
    for (int o = 16; o > 0; o >>= 1) s += __shfl_down_sync(0xffffffffu, s, o);
    if ((t & 31) == 0) warpsum[t >> 5] = s;
    __syncthreads();
    if (t < SCAN_BLK / 32) {
        int ws = warpsum[t];
#pragma unroll
        for (int o = SCAN_BLK / 64; o > 0; o >>= 1)
            ws += __shfl_down_sync(0xffffffffu, ws, o);
        if (t == 0) g_bsum[b] = ws;
    }
}

__global__ void k_scanB() {
    __shared__ int sh[64];
    int t = threadIdx.x;
    int v = (t < SCAN_NBLK) ? g_bsum[t] : 0;
    sh[t] = v;
    __syncthreads();
#pragma unroll
    for (int d = 1; d < 64; d <<= 1) {
        int u = (t >= d) ? sh[t - d] : 0;
        __syncthreads();
        sh[t] += u;
        __syncthreads();
    }
    if (t < SCAN_NBLK) g_bbase[t] = (t > 0) ? sh[t - 1] : 0;
    if (t == 63) g_off[N_NODES] = sh[SCAN_NBLK - 1];
}

__global__ __launch_bounds__(SCAN_BLK) void k_scanC() {
    __shared__ int sh[SCAN_BLK];
    int t = threadIdx.x, b = blockIdx.x;
    int idx = b * SCAN_CHUNK + t * SCAN_ITEMS;
    int4 v = (idx < N_NODES + 4) ? ((const int4*)g_deg)[idx >> 2]
                                 : make_int4(0, 0, 0, 0);
    int d0 = (idx + 0 < N_NODES) ? v.x : 0;
    int d1 = (idx + 1 < N_NODES) ? v.y : 0;
    int d2 = (idx + 2 < N_NODES) ? v.z : 0;
    int d3 = (idx + 3 < N_NODES) ? v.w : 0;
    sh[t] = d0 + d1 + d2 + d3;
    __syncthreads();
#pragma unroll
    for (int d = 1; d < SCAN_BLK; d <<= 1) {
        int u = (t >= d) ? sh[t - d] : 0;
        __syncthreads();
        sh[t] += u;
        __syncthreads();
    }
    int run = g_bbase[b] + ((t > 0) ? sh[t - 1] : 0);
    int dg[4] = {d0, d1, d2, d3};
#pragma unroll
    for (int j = 0; j < 4; j++) {
        int i = idx + j;
        if (i < N_NODES) {
            g_off[i] = run;
            g_cursor[i] = run;
            g_dinv[i] = rsqrtf((float)(dg[j] + 1));
            run += dg[j];
        }
    }
}

// ---------------------------------------------------------------------------
__global__ void k_fill(const void* __restrict__ ei) {
    int use64 = g_is64;
    int tid = blockIdx.x * blockDim.x + threadIdx.x;
    int stride = gridDim.x * blockDim.x;
    for (int e = tid; e < N_EDGES; e += stride) {
        unsigned s = (unsigned)edge_at(ei, use64, e);
        unsigned d = (unsigned)edge_at(ei, use64, (size_t)N_EDGES + e);
        if (d < N_NODES && s < N_NODES) {
            int pos = atomicAdd(&g_cursor[d], 1);
            g_csr_src[pos] = (int)s;
        }
    }
}

// ---------------------------------------------------------------------------
// K4: z = dinv * (x @ Wc).  8-row warp tiles + packed f32x2 FMAs.
// Weight float4 from LDS.128 reinterpreted as 2x f32x2 (zero pack cost);
// only the broadcast x scalar needs one mov.b64 dup per (k,r).
// ---------------------------------------------------------------------------
__global__ __launch_bounds__(256) void k_gemm1(const float* __restrict__ x,
                                               const float* __restrict__ Wc) {
    extern __shared__ float sm[];
    float* Ws = sm;                          // 16384 floats (64 KB)
    float* xt = sm + D * D;                  // 8 warps * 8 rows * 128
    int tid = threadIdx.x, warp = tid >> 5, lane = tid & 31;

    for (int i = tid; i < D * D / 4; i += 256)
        ((float4*)Ws)[i] = ((const float4*)Wc)[i];
    __syncthreads();

    float* xw = xt + warp * (RT * D);
    const int ngroups = (N_NODES + RT - 1) / RT;
    const int wstride = gridDim.x * 8;
    for (int g = blockIdx.x * 8 + warp; g < ngroups; g += wstride) {
        int row0 = g * RT;
#pragma unroll
        for (int r = 0; r < RT; r++) {
            int row = row0 + r;
            float4 v = (row < N_NODES) ? ((const float4*)(x + (size_t)row * D))[lane]
                                       : make_float4(0.f, 0.f, 0.f, 0.f);
            ((float4*)(xw + r * D))[lane] = v;
        }
        __syncwarp();

        unsigned long long a0[RT], a1[RT];
#pragma unroll
        for (int r = 0; r < RT; r++) { a0[r] = 0ull; a1[r] = 0ull; }
#pragma unroll 4
        for (int k = 0; k < D; k++) {
            ulonglong2 w = ((const ulonglong2*)(Ws + k * D))[lane];
#pragma unroll
            for (int r = 0; r < RT; r++) {
                unsigned xi = __float_as_uint(xw[r * D + k]);
                unsigned long long xp;
                PACK_DUP(xp, xi);
                FMA_X2(a0[r], xp, w.x);
                FMA_X2(a1[r], xp, w.y);
            }
        }
#pragma unroll
        for (int r = 0; r < RT; r++) {
            int row = row0 + r;
            if (row < N_NODES) {
                unsigned si = __float_as_uint(g_dinv[row]);
                unsigned long long sp, o0, o1;
                PACK_DUP(sp, si);
                MUL_X2(o0, a0[r], sp);
                MUL_X2(o1, a1[r], sp);
                ((ulonglong2*)(g_z + (size_t)row * D))[lane] = make_ulonglong2(o0, o1);
            }
        }
        __syncwarp();
    }
}

// ---------------------------------------------------------------------------
// K5 (fused): per 8-row warp tile — CSR gather of z, fold self-loop+bias,
//             then out = h @ (I+Wt) + x @ (W0-Wt), packed f32x2 FMAs.
// ---------------------------------------------------------------------------
__global__ __launch_bounds__(256) void k_final(const float* __restrict__ x,
                                               const float* __restrict__ bc,
                                               const float* __restrict__ W0,
                                               const float* __restrict__ Wt,
                                               float* __restrict__ out) {
    extern __shared__ float sm[];
    float* M1s = sm;                         // 16384
    float* M2s = sm + D * D;                 // 16384
    float* bcs = sm + 2 * D * D;             // 128
    float* tiles = bcs + D;                  // 8 warps * (2 * 8 * 128)
    int tid = threadIdx.x, warp = tid >> 5, lane = tid & 31;

    // Build M1 = Wt + I, M2 = W0 - Wt directly in smem.
    for (int i = tid; i < D * D / 4; i += 256) {
        float4 wt = ((const float4*)Wt)[i];
        float4 w0 = ((const float4*)W0)[i];
        int r = (i * 4) / D, c0 = (i * 4) % D;
        float m1v[4] = {wt.x, wt.y, wt.z, wt.w};
        int dd = r - c0;
        if (dd >= 0 && dd < 4) m1v[dd] += 1.0f;
        ((float4*)M1s)[i] = make_float4(m1v[0], m1v[1], m1v[2], m1v[3]);
        ((float4*)M2s)[i] = make_float4(w0.x - wt.x, w0.y - wt.y,
                                        w0.z - wt.z, w0.w - wt.w);
    }
    if (tid < D) bcs[tid] = bc[tid];
    __syncthreads();

    float* ht = tiles + warp * (2 * RT * D);
    float* xt = ht + RT * D;

    const int ngroups = (N_NODES + RT - 1) / RT;
    const int wstride = gridDim.x * 8;
    for (int g = blockIdx.x * 8 + warp; g < ngroups; g += wstride) {
        int row0 = g * RT;

        // ---- gather phase: h[r] = dinv*(z[row] + sum z[src]) + bc
#pragma unroll
        for (int r = 0; r < RT; r++) {
            int row = row0 + r;
            if (row >= N_NODES) {
                ((float4*)(ht + r * D))[lane] = make_float4(0.f, 0.f, 0.f, 0.f);
                ((float4*)(xt + r * D))[lane] = make_float4(0.f, 0.f, 0.f, 0.f);
                continue;
            }
            size_t base = (size_t)row * D;
            float4 acc = ((const float4*)(g_z + base))[lane];
            int e = g_off[row], end = g_off[row + 1];
            for (; e + 7 < end; e += 8) {
                int s0 = __ldg(&g_csr_src[e]);
                int s1 = __ldg(&g_csr_src[e + 1]);
                int s2 = __ldg(&g_csr_src[e + 2]);
                int s3 = __ldg(&g_csr_src[e + 3]);
                int s4 = __ldg(&g_csr_src[e + 4]);
                int s5 = __ldg(&g_csr_src[e + 5]);
                int s6 = __ldg(&g_csr_src[e + 6]);
                int s7 = __ldg(&g_csr_src[e + 7]);
                float4 v0 = ((const float4*)(g_z + (size_t)s0 * D))[lane];
                float4 v1 = ((const float4*)(g_z + (size_t)s1 * D))[lane];
                float4 v2 = ((const float4*)(g_z + (size_t)s2 * D))[lane];
                float4 v3 = ((const float4*)(g_z + (size_t)s3 * D))[lane];
                float4 v4 = ((const float4*)(g_z + (size_t)s4 * D))[lane];
                float4 v5 = ((const float4*)(g_z + (size_t)s5 * D))[lane];
                float4 v6 = ((const float4*)(g_z + (size_t)s6 * D))[lane];
                float4 v7 = ((const float4*)(g_z + (size_t)s7 * D))[lane];
                acc.x += ((v0.x + v1.x) + (v2.x + v3.x)) + ((v4.x + v5.x) + (v6.x + v7.x));
                acc.y += ((v0.y + v1.y) + (v2.y + v3.y)) + ((v4.y + v5.y) + (v6.y + v7.y));
                acc.z += ((v0.z + v1.z) + (v2.z + v3.z)) + ((v4.z + v5.z) + (v6.z + v7.z));
                acc.w += ((v0.w + v1.w) + (v2.w + v3.w)) + ((v4.w + v5.w) + (v6.w + v7.w));
            }
            for (; e < end; e++) {
                int s0 = __ldg(&g_csr_src[e]);
                float4 v0 = ((const float4*)(g_z + (size_t)s0 * D))[lane];
                acc.x += v0.x; acc.y += v0.y; acc.z += v0.z; acc.w += v0.w;
            }
            float s = g_dinv[row];
            float4 b4 = ((const float4*)bcs)[lane];
            float4 x4 = ((const float4*)(x + base))[lane];
            float4 h4;
            h4.x = s * acc.x + b4.x;
            h4.y = s * acc.y + b4.y;
            h4.z = s * acc.z + b4.z;
            h4.w = s * acc.w + b4.w;
            ((float4*)(ht + r * D))[lane] = h4;
            ((float4*)(xt + r * D))[lane] = x4;
        }
        __syncwarp();

        // ---- dual GEMM: o[r] = h[r] @ M1 + x[r] @ M2  (packed f32x2)
        unsigned long long o0[RT], o1[RT];
#pragma unroll
        for (int r = 0; r < RT; r++) { o0[r] = 0ull; o1[r] = 0ull; }
#pragma unroll 2
        for (int k = 0; k < D; k++) {
            ulonglong2 m1 = ((const ulonglong2*)(M1s + k * D))[lane];
            ulonglong2 m2 = ((const ulonglong2*)(M2s + k * D))[lane];
#pragma unroll
            for (int r = 0; r < RT; r++) {
                unsigned hi_ = __float_as_uint(ht[r * D + k]);
                unsigned xi_ = __float_as_uint(xt[r * D + k]);
                unsigned long long hp, xp;
                PACK_DUP(hp, hi_);
                PACK_DUP(xp, xi_);
                FMA_X2(o0[r], hp, m1.x);
                FMA_X2(o1[r], hp, m1.y);
                FMA_X2(o0[r], xp, m2.x);
                FMA_X2(o1[r], xp, m2.y);
            }
        }
#pragma unroll
        for (int r = 0; r < RT; r++) {
            int row = row0 + r;
            if (row < N_NODES)
                ((ulonglong2*)(out + (size_t)row * D))[lane] = make_ulonglong2(o0[r], o1[r]);
        }
        __syncwarp();
    }
}

// ---------------------------------------------------------------------------
extern "C" void kernel_launch(void* const* d_in, const int* in_sizes, int n_in,
                              void* d_out, int out_size) {
    const float* x  = (const float*)d_in[0];
    const void*  ei = d_in[1];
    const float* Wc = (const float*)d_in[2];
    const float* bc = (const float*)d_in[3];
    const float* W0 = (const float*)d_in[4];
    const float* Wt = (const float*)d_in[5];

    {
        const float* fx = nullptr; const void* fei = nullptr;
        const float* fbc = nullptr;
        const float* w[3] = {nullptr, nullptr, nullptr}; int nw = 0;
        for (int i = 0; i < n_in; i++) {
            int sz = in_sizes[i];
            if (sz == N_NODES * D)                           fx  = (const float*)d_in[i];
            else if (sz == 2 * N_EDGES || sz == 4 * N_EDGES) fei = d_in[i];
            else if (sz == D)                                fbc = (const float*)d_in[i];
            else if (sz == D * D && nw < 3)                  w[nw++] = (const float*)d_in[i];
        }
        if (fx)  x  = fx;
        if (fei) ei = fei;
        if (fbc) bc = fbc;
        if (nw == 3) { Wc = w[0]; W0 = w[1]; Wt = w[2]; }
    }
    float* out = (float*)d_out;

    int smem_gemm1 = (D * D + 8 * RT * D) * (int)sizeof(float);                // 98,304 B
    int smem_final = (2 * D * D + D + 8 * 2 * RT * D) * (int)sizeof(float);    // 197,120 B
    cudaFuncSetAttribute(k_gemm1, cudaFuncAttributeMaxDynamicSharedMemorySize, smem_gemm1);
    cudaFuncSetAttribute(k_final, cudaFuncAttributeMaxDynamicSharedMemorySize, smem_final);

    k_detect<<<1, 256>>>((const long long*)ei);
    k_init<<<256, 256>>>();
    k_degree<<<1024, 256>>>(ei);
    k_scanA<<<SCAN_NBLK, SCAN_BLK>>>();
    k_scanB<<<1, 64>>>();
    k_scanC<<<SCAN_NBLK, SCAN_BLK>>>();
    k_fill<<<1024, 256>>>(ei);
    k_gemm1<<<296, 256, smem_gemm1>>>(x, Wc);
    k_final<<<148, 256, smem_final>>>(x, bc, W0, Wt, out);
}

// round 9
// speedup vs baseline: 2.0137x; 1.0265x over previous
#include <cuda_runtime.h>
#include <cstdint>

#define N_NODES 50000
#define N_EDGES 800000
#define D       128
#define RT      8                      // rows per warp tile

#define SCAN_ITEMS 4
#define SCAN_BLK   256
#define SCAN_CHUNK (SCAN_BLK * SCAN_ITEMS)                       // 1024
#define SCAN_NBLK  ((N_NODES + SCAN_CHUNK - 1) / SCAN_CHUNK)     // 49

#define FILL_BLOCKS 64
#define GEMM_BLOCKS 296

// ---- packed f32x2 helpers (FFMA2: 2 fp32 FMAs per issue slot) ----
#define FMA_X2(acc, a, b) \
    asm("fma.rn.f32x2 %0, %1, %2, %0;" : "+l"(acc) : "l"(a), "l"(b))
#define MUL_X2(out, a, b) \
    asm("mul.rn.f32x2 %0, %1, %2;" : "=l"(out) : "l"(a), "l"(b))
#define PACK_DUP(out, xi) \
    asm("mov.b64 %0, {%1, %1};" : "=l"(out) : "r"(xi))

// ---- scratch (device globals; no allocation allowed) ----
__device__ __align__(16) float g_z[(size_t)N_NODES * D];    // z = dinv * (x @ Wc)
__device__ __align__(16) float g_dinv[N_NODES];
__device__ __align__(16) int   g_deg[N_NODES + 4];          // zero-init; re-zeroed by scanC
__device__ int   g_off[N_NODES + 1];
__device__ int   g_cursor[N_NODES];
__device__ int   g_csr_src[N_EDGES];
__device__ int   g_bsum[SCAN_NBLK];

// ---------------------------------------------------------------------------
// Per-block edge dtype detection: indices < 50000 => genuine int64 has all
// high words zero across the first 64 words; int32 data essentially never does.
// ---------------------------------------------------------------------------
__device__ __forceinline__ int detect_is64_block(const void* ei, int* s_flag) {
    if (threadIdx.x == 0) {
        const long long* p = (const long long*)ei;
        int use64 = 1;
        for (int i = 0; i < 64; i++)
            if ((unsigned long long)p[i] >> 32) { use64 = 0; break; }
        *s_flag = use64;
    }
    __syncthreads();
    return *s_flag;
}

__device__ __forceinline__ int edge_at(const void* ei, int use64, size_t idx) {
    return use64 ? (int)((const long long*)ei)[idx]
                 : ((const int*)ei)[idx];
}

// ---------------------------------------------------------------------------
// K1: in-degree histogram over dst (int atomics; range-guarded)
// ---------------------------------------------------------------------------
__global__ void k_degree(const void* __restrict__ ei) {
    __shared__ int s_flag;
    int use64 = detect_is64_block(ei, &s_flag);
    int tid = blockIdx.x * blockDim.x + threadIdx.x;
    int stride = gridDim.x * blockDim.x;
    for (int e = tid; e < N_EDGES; e += stride) {
        unsigned d = (unsigned)edge_at(ei, use64, (size_t)N_EDGES + e);
        if (d < N_NODES) atomicAdd(&g_deg[d], 1);
    }
}

// ---------------------------------------------------------------------------
// K2a: per-block reduce of deg (int4 coalesced) -> g_bsum
// ---------------------------------------------------------------------------
__global__ __launch_bounds__(SCAN_BLK) void k_scanA() {
    __shared__ int warpsum[SCAN_BLK / 32];
    int t = threadIdx.x, b = blockIdx.x;
    int idx = b * SCAN_CHUNK + t * SCAN_ITEMS;
    int4 v = (idx < N_NODES + 4) ? ((const int4*)g_deg)[idx >> 2]
                                 : make_int4(0, 0, 0, 0);
    int s = 0;
    if (idx + 0 < N_NODES) s += v.x;
    if (idx + 1 < N_NODES) s += v.y;
    if (idx + 2 < N_NODES) s += v.z;
    if (idx + 3 < N_NODES) s += v.w;
#pragma unroll
    for (int o = 16; o > 0; o >>= 1) s += __shfl_down_sync(0xffffffffu, s, o);
    if ((t & 31) == 0) warpsum[t >> 5] = s;
    __syncthreads();
    if (t < SCAN_BLK / 32) {
        int ws = warpsum[t];
#pragma unroll
        for (int o = SCAN_BLK / 64; o > 0; o >>= 1)
            ws += __shfl_down_sync(0xffffffffu, ws, o);
        if (t == 0) g_bsum[b] = ws;
    }
}

// ---------------------------------------------------------------------------
// K2c: block base from g_bsum prefix + local scan -> off, cursor, dinv.
// Also re-zeroes g_deg for the next graph replay (deg consumed here).
// ---------------------------------------------------------------------------
__global__ __launch_bounds__(SCAN_BLK) void k_scanC() {
    __shared__ int sh[SCAN_BLK];
    __shared__ int s_base;
    int t = threadIdx.x, b = blockIdx.x;

    if (t < 32) {
        int v = 0;
        for (int i = t; i < b; i += 32) v += g_bsum[i];
#pragma unroll
        for (int o = 16; o > 0; o >>= 1) v += __shfl_down_sync(0xffffffffu, v, o);
        if (t == 0) s_base = v;
    }

    int idx = b * SCAN_CHUNK + t * SCAN_ITEMS;
    int4 v = (idx < N_NODES + 4) ? ((const int4*)g_deg)[idx >> 2]
                                 : make_int4(0, 0, 0, 0);
    if (idx < N_NODES + 4)
        ((int4*)g_deg)[idx >> 2] = make_int4(0, 0, 0, 0);   // reset for next replay
    int d0 = (idx + 0 < N_NODES) ? v.x : 0;
    int d1 = (idx + 1 < N_NODES) ? v.y : 0;
    int d2 = (idx + 2 < N_NODES) ? v.z : 0;
    int d3 = (idx + 3 < N_NODES) ? v.w : 0;
    sh[t] = d0 + d1 + d2 + d3;
    __syncthreads();
#pragma unroll
    for (int d = 1; d < SCAN_BLK; d <<= 1) {
        int u = (t >= d) ? sh[t - d] : 0;
        __syncthreads();
        sh[t] += u;
        __syncthreads();
    }
    int run = s_base + ((t > 0) ? sh[t - 1] : 0);
    int dg[4] = {d0, d1, d2, d3};
#pragma unroll
    for (int j = 0; j < 4; j++) {
        int i = idx + j;
        if (i < N_NODES) {
            g_off[i] = run;
            g_cursor[i] = run;
            g_dinv[i] = rsqrtf((float)(dg[j] + 1));
            run += dg[j];
        }
    }
    if (b == SCAN_NBLK - 1 && t == SCAN_BLK - 1) g_off[N_NODES] = run;
}

// ---------------------------------------------------------------------------
// K3 (fused): blocks [0,FILL_BLOCKS) fill CSR; the rest run gemm1
//             (z = dinv * (x @ Wc), 8-row warp tiles, packed f32x2).
// ---------------------------------------------------------------------------
__global__ __launch_bounds__(256) void k_work(const float* __restrict__ x,
                                              const float* __restrict__ Wc,
                                              const void* __restrict__ ei) {
    extern __shared__ float sm[];

    if (blockIdx.x < FILL_BLOCKS) {
        // ---- CSR fill path
        __shared__ int s_flag;
        int use64 = detect_is64_block(ei, &s_flag);
        int tid = blockIdx.x * blockDim.x + threadIdx.x;
        int stride = FILL_BLOCKS * blockDim.x;
        for (int e = tid; e < N_EDGES; e += stride) {
            unsigned s = (unsigned)edge_at(ei, use64, e);
            unsigned d = (unsigned)edge_at(ei, use64, (size_t)N_EDGES + e);
            if (d < N_NODES && s < N_NODES) {
                int pos = atomicAdd(&g_cursor[d], 1);
                g_csr_src[pos] = (int)s;
            }
        }
        return;
    }

    // ---- gemm1 path
    float* Ws = sm;                          // 16384 floats
    float* xt = sm + D * D;                  // 8 warps * 8 rows * 128
    int tid = threadIdx.x, warp = tid >> 5, lane = tid & 31;
    int bid = blockIdx.x - FILL_BLOCKS;

    for (int i = tid; i < D * D / 4; i += 256)
        ((float4*)Ws)[i] = ((const float4*)Wc)[i];
    __syncthreads();

    float* xw = xt + warp * (RT * D);
    const int ngroups = (N_NODES + RT - 1) / RT;
    const int wstride = GEMM_BLOCKS * 8;
    for (int g = bid * 8 + warp; g < ngroups; g += wstride) {
        int row0 = g * RT;
#pragma unroll
        for (int r = 0; r < RT; r++) {
            int row = row0 + r;
            float4 v = (row < N_NODES) ? ((const float4*)(x + (size_t)row * D))[lane]
                                       : make_float4(0.f, 0.f, 0.f, 0.f);
            ((float4*)(xw + r * D))[lane] = v;
        }
        __syncwarp();

        unsigned long long a0[RT], a1[RT];
#pragma unroll
        for (int r = 0; r < RT; r++) { a0[r] = 0ull; a1[r] = 0ull; }
#pragma unroll 4
        for (int k = 0; k < D; k++) {
            ulonglong2 w = ((const ulonglong2*)(Ws + k * D))[lane];
#pragma unroll
            for (int r = 0; r < RT; r++) {
                unsigned xi = __float_as_uint(xw[r * D + k]);
                unsigned long long xp;
                PACK_DUP(xp, xi);
                FMA_X2(a0[r], xp, w.x);
                FMA_X2(a1[r], xp, w.y);
            }
        }
#pragma unroll
        for (int r = 0; r < RT; r++) {
            int row = row0 + r;
            if (row < N_NODES) {
                unsigned si = __float_as_uint(g_dinv[row]);
                unsigned long long sp, o0, o1;
                PACK_DUP(sp, si);
                MUL_X2(o0, a0[r], sp);
                MUL_X2(o1, a1[r], sp);
                ((ulonglong2*)(g_z + (size_t)row * D))[lane] = make_ulonglong2(o0, o1);
            }
        }
        __syncwarp();
    }
}

// ---------------------------------------------------------------------------
// K5 (fused): per 8-row warp tile — pipelined CSR gather of z (coalesced idx
// into smem double-buffer, prefetched one row ahead), fold self-loop+bias,
// then out = h @ (I+Wt) + x @ (W0-Wt) with packed f32x2.
// ---------------------------------------------------------------------------
__global__ __launch_bounds__(256) void k_final(const float* __restrict__ x,
                                               const float* __restrict__ bc,
                                               const float* __restrict__ W0,
                                               const float* __restrict__ Wt,
                                               float* __restrict__ out) {
    extern __shared__ float sm[];
    float* M1s = sm;                         // 16384
    float* M2s = sm + D * D;                 // 16384
    float* bcs = sm + 2 * D * D;             // 128
    float* tiles = bcs + D;                  // 8 warps * (2 * 8 * 128) = 16384
    int*   ibase = (int*)(tiles + 8 * 2 * RT * D);   // 8 warps * 64 ints
    int tid = threadIdx.x, warp = tid >> 5, lane = tid & 31;

    for (int i = tid; i < D * D / 4; i += 256) {
        float4 wt = ((const float4*)Wt)[i];
        float4 w0 = ((const float4*)W0)[i];
        int r = (i * 4) / D, c0 = (i * 4) % D;
        float m1v[4] = {wt.x, wt.y, wt.z, wt.w};
        int dd = r - c0;
        if (dd >= 0 && dd < 4) m1v[dd] += 1.0f;
        ((float4*)M1s)[i] = make_float4(m1v[0], m1v[1], m1v[2], m1v[3]);
        ((float4*)M2s)[i] = make_float4(w0.x - wt.x, w0.y - wt.y,
                                        w0.z - wt.z, w0.w - wt.w);
    }
    if (tid < D) bcs[tid] = bc[tid];
    __syncthreads();

    float* ht = tiles + warp * (2 * RT * D);
    float* xt = ht + RT * D;
    int*   ibuf = ibase + warp * 64;          // two 32-entry halves

    const int ngroups = (N_NODES + RT - 1) / RT;
    const int wstride = gridDim.x * 8;
    for (int g = blockIdx.x * 8 + warp; g < ngroups; g += wstride) {
        int row0 = g * RT;

        // fetch 9 CSR offsets in one coalesced round
        int off_l = 0;
        if (lane <= RT) {
            int rr = row0 + lane;
            off_l = __ldg(&g_off[rr < N_NODES ? rr : N_NODES]);
        }
        int rowE[RT + 1];
#pragma unroll
        for (int r = 0; r <= RT; r++)
            rowE[r] = __shfl_sync(0xffffffffu, off_l, r);

        // prefetch row 0's indices (up to 32, coalesced)
        {
            int n0 = rowE[1] - rowE[0];
            if (lane < (n0 < 32 ? n0 : 32)) ibuf[lane] = __ldg(&g_csr_src[rowE[0] + lane]);
        }

        // ---- gather phase with one-row-ahead idx prefetch
#pragma unroll
        for (int r = 0; r < RT; r++) {
            __syncwarp();
            int* cur = ibuf + ((r & 1) << 5);
            if (r + 1 < RT) {
                int* nxt = ibuf + (((r + 1) & 1) << 5);
                int nn = rowE[r + 2] - rowE[r + 1];
                if (lane < (nn < 32 ? nn : 32))
                    nxt[lane] = __ldg(&g_csr_src[rowE[r + 1] + lane]);
            }

            int row = row0 + r;
            if (row >= N_NODES) {
                ((float4*)(ht + r * D))[lane] = make_float4(0.f, 0.f, 0.f, 0.f);
                ((float4*)(xt + r * D))[lane] = make_float4(0.f, 0.f, 0.f, 0.f);
                continue;
            }
            size_t base = (size_t)row * D;
            float4 acc = ((const float4*)(g_z + base))[lane];
            int n = rowE[r + 1] - rowE[r];
            int m = n < 32 ? n : 32;
            int i = 0;
            for (; i + 7 < m; i += 8) {
                int s0 = cur[i];     int s1 = cur[i + 1];
                int s2 = cur[i + 2]; int s3 = cur[i + 3];
                int s4 = cur[i + 4]; int s5 = cur[i + 5];
                int s6 = cur[i + 6]; int s7 = cur[i + 7];
                float4 v0 = ((const float4*)(g_z + (size_t)s0 * D))[lane];
                float4 v1 = ((const float4*)(g_z + (size_t)s1 * D))[lane];
                float4 v2 = ((const float4*)(g_z + (size_t)s2 * D))[lane];
                float4 v3 = ((const float4*)(g_z + (size_t)s3 * D))[lane];
                float4 v4 = ((const float4*)(g_z + (size_t)s4 * D))[lane];
                float4 v5 = ((const float4*)(g_z + (size_t)s5 * D))[lane];
                float4 v6 = ((const float4*)(g_z + (size_t)s6 * D))[lane];
                float4 v7 = ((const float4*)(g_z + (size_t)s7 * D))[lane];
                acc.x += ((v0.x + v1.x) + (v2.x + v3.x)) + ((v4.x + v5.x) + (v6.x + v7.x));
                acc.y += ((v0.y + v1.y) + (v2.y + v3.y)) + ((v4.y + v5.y) + (v6.y + v7.y));
                acc.z += ((v0.z + v1.z) + (v2.z + v3.z)) + ((v4.z + v5.z) + (v6.z + v7.z));
                acc.w += ((v0.w + v1.w) + (v2.w + v3.w)) + ((v4.w + v5.w) + (v6.w + v7.w));
            }
            for (; i < m; i++) {
                int s0 = cur[i];
                float4 v0 = ((const float4*)(g_z + (size_t)s0 * D))[lane];
                acc.x += v0.x; acc.y += v0.y; acc.z += v0.z; acc.w += v0.w;
            }
            // rare tail: degree > 32
            for (int e = rowE[r] + 32; e < rowE[r + 1]; e++) {
                int s0 = __ldg(&g_csr_src[e]);
                float4 v0 = ((const float4*)(g_z + (size_t)s0 * D))[lane];
                acc.x += v0.x; acc.y += v0.y; acc.z += v0.z; acc.w += v0.w;
            }

            float s = g_dinv[row];
            float4 b4 = ((const float4*)bcs)[lane];
            float4 x4 = ((const float4*)(x + base))[lane];
            float4 h4;
            h4.x = s * acc.x + b4.x;
            h4.y = s * acc.y + b4.y;
            h4.z = s * acc.z + b4.z;
            h4.w = s * acc.w + b4.w;
            ((float4*)(ht + r * D))[lane] = h4;
            ((float4*)(xt + r * D))[lane] = x4;
        }
        __syncwarp();

        // ---- dual GEMM: o[r] = h[r] @ M1 + x[r] @ M2  (packed f32x2)
        unsigned long long o0[RT], o1[RT];
#pragma unroll
        for (int r = 0; r < RT; r++) { o0[r] = 0ull; o1[r] = 0ull; }
#pragma unroll 2
        for (int k = 0; k < D; k++) {
            ulonglong2 m1 = ((const ulonglong2*)(M1s + k * D))[lane];
            ulonglong2 m2 = ((const ulonglong2*)(M2s + k * D))[lane];
#pragma unroll
            for (int r = 0; r < RT; r++) {
                unsigned hi_ = __float_as_uint(ht[r * D + k]);
                unsigned xi_ = __float_as_uint(xt[r * D + k]);
                unsigned long long hp, xp;
                PACK_DUP(hp, hi_);
                PACK_DUP(xp, xi_);
                FMA_X2(o0[r], hp, m1.x);
                FMA_X2(o1[r], hp, m1.y);
                FMA_X2(o0[r], xp, m2.x);
                FMA_X2(o1[r], xp, m2.y);
            }
        }
#pragma unroll
        for (int r = 0; r < RT; r++) {
            int row = row0 + r;
            if (row < N_NODES)
                ((ulonglong2*)(out + (size_t)row * D))[lane] = make_ulonglong2(o0[r], o1[r]);
        }
        __syncwarp();
    }
}

// ---------------------------------------------------------------------------
extern "C" void kernel_launch(void* const* d_in, const int* in_sizes, int n_in,
                              void* d_out, int out_size) {
    const float* x  = (const float*)d_in[0];
    const void*  ei = d_in[1];
    const float* Wc = (const float*)d_in[2];
    const float* bc = (const float*)d_in[3];
    const float* W0 = (const float*)d_in[4];
    const float* Wt = (const float*)d_in[5];

    {
        const float* fx = nullptr; const void* fei = nullptr;
        const float* fbc = nullptr;
        const float* w[3] = {nullptr, nullptr, nullptr}; int nw = 0;
        for (int i = 0; i < n_in; i++) {
            int sz = in_sizes[i];
            if (sz == N_NODES * D)                           fx  = (const float*)d_in[i];
            else if (sz == 2 * N_EDGES || sz == 4 * N_EDGES) fei = d_in[i];
            else if (sz == D)                                fbc = (const float*)d_in[i];
            else if (sz == D * D && nw < 3)                  w[nw++] = (const float*)d_in[i];
        }
        if (fx)  x  = fx;
        if (fei) ei = fei;
        if (fbc) bc = fbc;
        if (nw == 3) { Wc = w[0]; W0 = w[1]; Wt = w[2]; }
    }
    float* out = (float*)d_out;

    int smem_work  = (D * D + 8 * RT * D) * (int)sizeof(float);               // 98,304 B
    int smem_final = (2 * D * D + D + 8 * 2 * RT * D) * (int)sizeof(float)
                     + 8 * 64 * (int)sizeof(int);                              // 199,168 B
    cudaFuncSetAttribute(k_work, cudaFuncAttributeMaxDynamicSharedMemorySize, smem_work);
    cudaFuncSetAttribute(k_final, cudaFuncAttributeMaxDynamicSharedMemorySize, smem_final);

    k_degree<<<512, 256>>>(ei);
    k_scanA<<<SCAN_NBLK, SCAN_BLK>>>();
    k_scanC<<<SCAN_NBLK, SCAN_BLK>>>();
    k_work<<<FILL_BLOCKS + GEMM_BLOCKS, 256, smem_work>>>(x, Wc, ei);
    k_final<<<148, 256, smem_final>>>(x, bc, W0, Wt, out);
}

// round 10
// speedup vs baseline: 2.1438x; 1.0646x over previous
#include <cuda_runtime.h>
#include <cstdint>

#define N_NODES 50000
#define N_EDGES 800000
#define D       128
#define RT      8                      // rows per warp tile (gemm1)
#define RTF     4                      // rows per warp tile (final)

#define SCAN_ITEMS 4
#define SCAN_BLK   256
#define SCAN_CHUNK (SCAN_BLK * SCAN_ITEMS)                       // 1024
#define SCAN_NBLK  ((N_NODES + SCAN_CHUNK - 1) / SCAN_CHUNK)     // 49

#define FILL_BLOCKS 96
#define GEMM_BLOCKS 348

// ---- packed f32x2 helpers (FFMA2: 2 fp32 FMAs per issue slot) ----
#define FMA_X2(acc, a, b) \
    asm("fma.rn.f32x2 %0, %1, %2, %0;" : "+l"(acc) : "l"(a), "l"(b))
#define MUL_X2(out, a, b) \
    asm("mul.rn.f32x2 %0, %1, %2;" : "=l"(out) : "l"(a), "l"(b))
#define PACK_DUP(out, xi) \
    asm("mov.b64 %0, {%1, %1};" : "=l"(out) : "r"(xi))

__device__ __forceinline__ float f4c(const float4& v, int kk) {
    return kk == 0 ? v.x : kk == 1 ? v.y : kk == 2 ? v.z : v.w;
}

// ---- scratch (device globals; no allocation allowed) ----
__device__ __align__(16) float g_z[(size_t)N_NODES * D];
__device__ __align__(16) float g_dinv[N_NODES];
__device__ __align__(16) int   g_deg[N_NODES + 4];          // zero-init; re-zeroed by scanC
__device__ int   g_off[N_NODES + 1];
__device__ int   g_cursor[N_NODES];
__device__ int   g_csr_src[N_EDGES];
__device__ int   g_bsum[SCAN_NBLK];

// ---------------------------------------------------------------------------
__device__ __forceinline__ int detect_is64_block(const void* ei, int* s_flag) {
    if (threadIdx.x == 0) {
        const long long* p = (const long long*)ei;
        int use64 = 1;
        for (int i = 0; i < 64; i++)
            if ((unsigned long long)p[i] >> 32) { use64 = 0; break; }
        *s_flag = use64;
    }
    __syncthreads();
    return *s_flag;
}

__device__ __forceinline__ int edge_at(const void* ei, int use64, size_t idx) {
    return use64 ? (int)((const long long*)ei)[idx]
                 : ((const int*)ei)[idx];
}

// ---------------------------------------------------------------------------
__global__ void k_degree(const void* __restrict__ ei) {
    __shared__ int s_flag;
    int use64 = detect_is64_block(ei, &s_flag);
    int tid = blockIdx.x * blockDim.x + threadIdx.x;
    int stride = gridDim.x * blockDim.x;
    for (int e = tid; e < N_EDGES; e += stride) {
        unsigned d = (unsigned)edge_at(ei, use64, (size_t)N_EDGES + e);
        if (d < N_NODES) atomicAdd(&g_deg[d], 1);
    }
}

// ---------------------------------------------------------------------------
__global__ __launch_bounds__(SCAN_BLK) void k_scanA() {
    __shared__ int warpsum[SCAN_BLK / 32];
    int t = threadIdx.x, b = blockIdx.x;
    int idx = b * SCAN_CHUNK + t * SCAN_ITEMS;
    int4 v = (idx < N_NODES + 4) ? ((const int4*)g_deg)[idx >> 2]
                                 : make_int4(0, 0, 0, 0);
    int s = 0;
    if (idx + 0 < N_NODES) s += v.x;
    if (idx + 1 < N_NODES) s += v.y;
    if (idx + 2 < N_NODES) s += v.z;
    if (idx + 3 < N_NODES) s += v.w;
#pragma unroll
    for (int o = 16; o > 0; o >>= 1) s += __shfl_down_sync(0xffffffffu, s, o);
    if ((t & 31) == 0) warpsum[t >> 5] = s;
    __syncthreads();
    if (t < SCAN_BLK / 32) {
        int ws = warpsum[t];
#pragma unroll
        for (int o = SCAN_BLK / 64; o > 0; o >>= 1)
            ws += __shfl_down_sync(0xffffffffu, ws, o);
        if (t == 0) g_bsum[b] = ws;
    }
}

// ---------------------------------------------------------------------------
__global__ __launch_bounds__(SCAN_BLK) void k_scanC() {
    __shared__ int sh[SCAN_BLK];
    __shared__ int s_base;
    int t = threadIdx.x, b = blockIdx.x;

    if (t < 32) {
        int v = 0;
        for (int i = t; i < b; i += 32) v += g_bsum[i];
#pragma unroll
        for (int o = 16; o > 0; o >>= 1) v += __shfl_down_sync(0xffffffffu, v, o);
        if (t == 0) s_base = v;
    }

    int idx = b * SCAN_CHUNK + t * SCAN_ITEMS;
    int4 v = (idx < N_NODES + 4) ? ((const int4*)g_deg)[idx >> 2]
                                 : make_int4(0, 0, 0, 0);
    if (idx < N_NODES + 4)
        ((int4*)g_deg)[idx >> 2] = make_int4(0, 0, 0, 0);
    int d0 = (idx + 0 < N_NODES) ? v.x : 0;
    int d1 = (idx + 1 < N_NODES) ? v.y : 0;
    int d2 = (idx + 2 < N_NODES) ? v.z : 0;
    int d3 = (idx + 3 < N_NODES) ? v.w : 0;
    sh[t] = d0 + d1 + d2 + d3;
    __syncthreads();
#pragma unroll
    for (int d = 1; d < SCAN_BLK; d <<= 1) {
        int u = (t >= d) ? sh[t - d] : 0;
        __syncthreads();
        sh[t] += u;
        __syncthreads();
    }
    int run = s_base + ((t > 0) ? sh[t - 1] : 0);
    int dg[4] = {d0, d1, d2, d3};
#pragma unroll
    for (int j = 0; j < 4; j++) {
        int i = idx + j;
        if (i < N_NODES) {
            g_off[i] = run;
            g_cursor[i] = run;
            g_dinv[i] = rsqrtf((float)(dg[j] + 1));
            run += dg[j];
        }
    }
    if (b == SCAN_NBLK - 1 && t == SCAN_BLK - 1) g_off[N_NODES] = run;
}

// ---------------------------------------------------------------------------
// K3 (fused): blocks [0,FILL_BLOCKS) fill CSR; the rest run gemm1.
// gemm1: weights in smem only (64 KB -> 3 CTAs/SM); x via uniform-address
// float4 LDG broadcasts, 8-row warp tiles, packed f32x2.
// ---------------------------------------------------------------------------
__global__ __launch_bounds__(256, 3) void k_work(const float* __restrict__ x,
                                                 const float* __restrict__ Wc,
                                                 const void* __restrict__ ei) {
    extern __shared__ float sm[];

    if (blockIdx.x < FILL_BLOCKS) {
        __shared__ int s_flag;
        int use64 = detect_is64_block(ei, &s_flag);
        int tid = blockIdx.x * blockDim.x + threadIdx.x;
        int stride = FILL_BLOCKS * blockDim.x;
        for (int e = tid; e < N_EDGES; e += stride) {
            unsigned s = (unsigned)edge_at(ei, use64, e);
            unsigned d = (unsigned)edge_at(ei, use64, (size_t)N_EDGES + e);
            if (d < N_NODES && s < N_NODES) {
                int pos = atomicAdd(&g_cursor[d], 1);
                g_csr_src[pos] = (int)s;
            }
        }
        return;
    }

    float* Ws = sm;                          // 16384 floats = 64 KB
    int tid = threadIdx.x, warp = tid >> 5, lane = tid & 31;
    int bid = blockIdx.x - FILL_BLOCKS;

    for (int i = tid; i < D * D / 4; i += 256)
        ((float4*)Ws)[i] = ((const float4*)Wc)[i];
    __syncthreads();

    const int ngroups = (N_NODES + RT - 1) / RT;
    const int wstride = GEMM_BLOCKS * 8;
    for (int g = bid * 8 + warp; g < ngroups; g += wstride) {
        int row0 = g * RT;

        unsigned long long a0[RT], a1[RT];
#pragma unroll
        for (int r = 0; r < RT; r++) { a0[r] = 0ull; a1[r] = 0ull; }

#pragma unroll 4
        for (int j = 0; j < D / 4; j++) {
            float4 xv[RT];
#pragma unroll
            for (int r = 0; r < RT; r++) {
                int row = row0 + r;
                xv[r] = (row < N_NODES)
                      ? __ldg(&((const float4*)(x + (size_t)row * D))[j])
                      : make_float4(0.f, 0.f, 0.f, 0.f);
            }
#pragma unroll
            for (int kk = 0; kk < 4; kk++) {
                int k = 4 * j + kk;
                ulonglong2 w = ((const ulonglong2*)(Ws + k * D))[lane];
#pragma unroll
                for (int r = 0; r < RT; r++) {
                    unsigned xi = __float_as_uint(f4c(xv[r], kk));
                    unsigned long long xp;
                    PACK_DUP(xp, xi);
                    FMA_X2(a0[r], xp, w.x);
                    FMA_X2(a1[r], xp, w.y);
                }
            }
        }
#pragma unroll
        for (int r = 0; r < RT; r++) {
            int row = row0 + r;
            if (row < N_NODES) {
                unsigned si = __float_as_uint(g_dinv[row]);
                unsigned long long sp, o0, o1;
                PACK_DUP(sp, si);
                MUL_X2(o0, a0[r], sp);
                MUL_X2(o1, a1[r], sp);
                ((ulonglong2*)(g_z + (size_t)row * D))[lane] = make_ulonglong2(o0, o1);
            }
        }
    }
}

// ---------------------------------------------------------------------------
// K5: 1024-thread blocks (32 warps/SM), RTF=4 rows per warp tile.
// Gather of z into smem h-tile (pipelined idx prefetch), epilogue
// out = h @ (I+Wt) + x @ (W0-Wt) with x via float4 LDG broadcasts.
// ---------------------------------------------------------------------------
__global__ __launch_bounds__(1024, 1) void k_final(const float* __restrict__ x,
                                                   const float* __restrict__ bc,
                                                   const float* __restrict__ W0,
                                                   const float* __restrict__ Wt,
                                                   float* __restrict__ out) {
    extern __shared__ float sm[];
    float* M1s = sm;                          // 16384
    float* M2s = sm + D * D;                  // 16384
    float* bcs = sm + 2 * D * D;              // 128
    float* ht  = bcs + D;                     // 32 warps * RTF * 128 = 16384
    int*   ibase = (int*)(ht + 32 * RTF * D); // 32 warps * 64 ints
    int tid = threadIdx.x, warp = tid >> 5, lane = tid & 31;

    for (int i = tid; i < D * D / 4; i += 1024) {
        float4 wt = ((const float4*)Wt)[i];
        float4 w0 = ((const float4*)W0)[i];
        int r = (i * 4) / D, c0 = (i * 4) % D;
        float m1v[4] = {wt.x, wt.y, wt.z, wt.w};
        int dd = r - c0;
        if (dd >= 0 && dd < 4) m1v[dd] += 1.0f;
        ((float4*)M1s)[i] = make_float4(m1v[0], m1v[1], m1v[2], m1v[3]);
        ((float4*)M2s)[i] = make_float4(w0.x - wt.x, w0.y - wt.y,
                                        w0.z - wt.z, w0.w - wt.w);
    }
    if (tid < D) bcs[tid] = bc[tid];
    __syncthreads();

    float* htw  = ht + warp * (RTF * D);
    int*   ibuf = ibase + warp * 64;          // two 32-entry halves

    const int ngroups = (N_NODES + RTF - 1) / RTF;
    const int wstride = gridDim.x * 32;
    for (int g = blockIdx.x * 32 + warp; g < ngroups; g += wstride) {
        int row0 = g * RTF;

        // fetch RTF+1 CSR offsets in one coalesced round
        int off_l = 0;
        if (lane <= RTF) {
            int rr = row0 + lane;
            off_l = __ldg(&g_off[rr < N_NODES ? rr : N_NODES]);
        }
        int rowE[RTF + 1];
#pragma unroll
        for (int r = 0; r <= RTF; r++)
            rowE[r] = __shfl_sync(0xffffffffu, off_l, r);

        {
            int n0 = rowE[1] - rowE[0];
            if (lane < (n0 < 32 ? n0 : 32)) ibuf[lane] = __ldg(&g_csr_src[rowE[0] + lane]);
        }

        // ---- gather phase with one-row-ahead idx prefetch
#pragma unroll
        for (int r = 0; r < RTF; r++) {
            __syncwarp();
            int* cur = ibuf + ((r & 1) << 5);
            if (r + 1 < RTF) {
                int* nxt = ibuf + (((r + 1) & 1) << 5);
                int nn = rowE[r + 2] - rowE[r + 1];
                if (lane < (nn < 32 ? nn : 32))
                    nxt[lane] = __ldg(&g_csr_src[rowE[r + 1] + lane]);
            }

            int row = row0 + r;
            if (row >= N_NODES) {
                ((float4*)(htw + r * D))[lane] = make_float4(0.f, 0.f, 0.f, 0.f);
                continue;
            }
            size_t base = (size_t)row * D;
            float4 acc = ((const float4*)(g_z + base))[lane];
            int n = rowE[r + 1] - rowE[r];
            int m = n < 32 ? n : 32;
            int i = 0;
            for (; i + 7 < m; i += 8) {
                int s0 = cur[i];     int s1 = cur[i + 1];
                int s2 = cur[i + 2]; int s3 = cur[i + 3];
                int s4 = cur[i + 4]; int s5 = cur[i + 5];
                int s6 = cur[i + 6]; int s7 = cur[i + 7];
                float4 v0 = ((const float4*)(g_z + (size_t)s0 * D))[lane];
                float4 v1 = ((const float4*)(g_z + (size_t)s1 * D))[lane];
                float4 v2 = ((const float4*)(g_z + (size_t)s2 * D))[lane];
                float4 v3 = ((const float4*)(g_z + (size_t)s3 * D))[lane];
                float4 v4 = ((const float4*)(g_z + (size_t)s4 * D))[lane];
                float4 v5 = ((const float4*)(g_z + (size_t)s5 * D))[lane];
                float4 v6 = ((const float4*)(g_z + (size_t)s6 * D))[lane];
                float4 v7 = ((const float4*)(g_z + (size_t)s7 * D))[lane];
                acc.x += ((v0.x + v1.x) + (v2.x + v3.x)) + ((v4.x + v5.x) + (v6.x + v7.x));
                acc.y += ((v0.y + v1.y) + (v2.y + v3.y)) + ((v4.y + v5.y) + (v6.y + v7.y));
                acc.z += ((v0.z + v1.z) + (v2.z + v3.z)) + ((v4.z + v5.z) + (v6.z + v7.z));
                acc.w += ((v0.w + v1.w) + (v2.w + v3.w)) + ((v4.w + v5.w) + (v6.w + v7.w));
            }
            for (; i < m; i++) {
                int s0 = cur[i];
                float4 v0 = ((const float4*)(g_z + (size_t)s0 * D))[lane];
                acc.x += v0.x; acc.y += v0.y; acc.z += v0.z; acc.w += v0.w;
            }
            for (int e = rowE[r] + 32; e < rowE[r + 1]; e++) {
                int s0 = __ldg(&g_csr_src[e]);
                float4 v0 = ((const float4*)(g_z + (size_t)s0 * D))[lane];
                acc.x += v0.x; acc.y += v0.y; acc.z += v0.z; acc.w += v0.w;
            }

            float s = g_dinv[row];
            float4 b4 = ((const float4*)bcs)[lane];
            float4 h4;
            h4.x = s * acc.x + b4.x;
            h4.y = s * acc.y + b4.y;
            h4.z = s * acc.z + b4.z;
            h4.w = s * acc.w + b4.w;
            ((float4*)(htw + r * D))[lane] = h4;
        }
        __syncwarp();

        // ---- dual GEMM: o[r] = h[r] @ M1 + x[r] @ M2  (packed f32x2,
        //      x via uniform-address float4 LDG broadcast)
        unsigned long long o0[RTF], o1[RTF];
#pragma unroll
        for (int r = 0; r < RTF; r++) { o0[r] = 0ull; o1[r] = 0ull; }
#pragma unroll 2
        for (int j = 0; j < D / 4; j++) {
            float4 xv[RTF];
#pragma unroll
            for (int r = 0; r < RTF; r++) {
                int row = row0 + r;
                xv[r] = (row < N_NODES)
                      ? __ldg(&((const float4*)(x + (size_t)row * D))[j])
                      : make_float4(0.f, 0.f, 0.f, 0.f);
            }
#pragma unroll
            for (int kk = 0; kk < 4; kk++) {
                int k = 4 * j + kk;
                ulonglong2 m1 = ((const ulonglong2*)(M1s + k * D))[lane];
                ulonglong2 m2 = ((const ulonglong2*)(M2s + k * D))[lane];
#pragma unroll
                for (int r = 0; r < RTF; r++) {
                    unsigned hi_ = __float_as_uint(htw[r * D + k]);
                    unsigned xi_ = __float_as_uint(f4c(xv[r], kk));
                    unsigned long long hp, xp;
                    PACK_DUP(hp, hi_);
                    PACK_DUP(xp, xi_);
                    FMA_X2(o0[r], hp, m1.x);
                    FMA_X2(o1[r], hp, m1.y);
                    FMA_X2(o0[r], xp, m2.x);
                    FMA_X2(o1[r], xp, m2.y);
                }
            }
        }
#pragma unroll
        for (int r = 0; r < RTF; r++) {
            int row = row0 + r;
            if (row < N_NODES)
                ((ulonglong2*)(out + (size_t)row * D))[lane] = make_ulonglong2(o0[r], o1[r]);
        }
        __syncwarp();
    }
}

// ---------------------------------------------------------------------------
extern "C" void kernel_launch(void* const* d_in, const int* in_sizes, int n_in,
                              void* d_out, int out_size) {
    const float* x  = (const float*)d_in[0];
    const void*  ei = d_in[1];
    const float* Wc = (const float*)d_in[2];
    const float* bc = (const float*)d_in[3];
    const float* W0 = (const float*)d_in[4];
    const float* Wt = (const float*)d_in[5];

    {
        const float* fx = nullptr; const void* fei = nullptr;
        const float* fbc = nullptr;
        const float* w[3] = {nullptr, nullptr, nullptr}; int nw = 0;
        for (int i = 0; i < n_in; i++) {
            int sz = in_sizes[i];
            if (sz == N_NODES * D)                           fx  = (const float*)d_in[i];
            else if (sz == 2 * N_EDGES || sz == 4 * N_EDGES) fei = d_in[i];
            else if (sz == D)                                fbc = (const float*)d_in[i];
            else if (sz == D * D && nw < 3)                  w[nw++] = (const float*)d_in[i];
        }
        if (fx)  x  = fx;
        if (fei) ei = fei;
        if (fbc) bc = fbc;
        if (nw == 3) { Wc = w[0]; W0 = w[1]; Wt = w[2]; }
    }
    float* out = (float*)d_out;

    int smem_work  = (D * D) * (int)sizeof(float);                             // 65,536 B
    int smem_final = (2 * D * D + D + 32 * RTF * D) * (int)sizeof(float)
                     + 32 * 64 * (int)sizeof(int);                             // 205,312 B
    cudaFuncSetAttribute(k_work, cudaFuncAttributeMaxDynamicSharedMemorySize, smem_work);
    cudaFuncSetAttribute(k_final, cudaFuncAttributeMaxDynamicSharedMemorySize, smem_final);

    k_degree<<<512, 256>>>(ei);
    k_scanA<<<SCAN_NBLK, SCAN_BLK>>>();
    k_scanC<<<SCAN_NBLK, SCAN_BLK>>>();
    k_work<<<FILL_BLOCKS + GEMM_BLOCKS, 256, smem_work>>>(x, Wc, ei);
    k_final<<<148, 1024, smem_final>>>(x, bc, W0, Wt, out);
}

// round 11
// speedup vs baseline: 2.3943x; 1.1168x over previous
#include <cuda_runtime.h>
#include <cstdint>

#define N_NODES 50000
#define N_EDGES 800000
#define D       128
#define RT      8                      // rows per warp tile (gemm1)
#define RTF     4                      // rows per warp tile (final)

#define SCAN_ITEMS 4
#define SCAN_BLK   256
#define SCAN_CHUNK (SCAN_BLK * SCAN_ITEMS)                       // 1024
#define SCAN_NBLK  ((N_NODES + SCAN_CHUNK - 1) / SCAN_CHUNK)     // 49

#define FILL_BLOCKS 96
#define GEMM_BLOCKS 296

// ---- packed f32x2 helpers (FFMA2: 2 fp32 FMAs per issue slot) ----
#define FMA_X2(acc, a, b) \
    asm("fma.rn.f32x2 %0, %1, %2, %0;" : "+l"(acc) : "l"(a), "l"(b))
#define MUL_X2(out, a, b) \
    asm("mul.rn.f32x2 %0, %1, %2;" : "=l"(out) : "l"(a), "l"(b))
#define PACK_DUP(out, xi) \
    asm("mov.b64 %0, {%1, %1};" : "=l"(out) : "r"(xi))

__device__ __forceinline__ float f4c(const float4& v, int kk) {
    return kk == 0 ? v.x : kk == 1 ? v.y : kk == 2 ? v.z : v.w;
}

// ---- scratch (device globals; no allocation allowed) ----
__device__ __align__(16) float g_z[(size_t)N_NODES * D];
__device__ __align__(16) float g_dinv[N_NODES];
__device__ __align__(16) int   g_deg[N_NODES + 4];          // zero-init; re-zeroed by scanC
__device__ int   g_off[N_NODES + 1];
__device__ int   g_cursor[N_NODES];
__device__ int   g_csr_src[N_EDGES];
__device__ int   g_bsum[SCAN_NBLK];

// ---------------------------------------------------------------------------
__device__ __forceinline__ int detect_is64_block(const void* ei, int* s_flag) {
    if (threadIdx.x == 0) {
        const long long* p = (const long long*)ei;
        int use64 = 1;
        for (int i = 0; i < 64; i++)
            if ((unsigned long long)p[i] >> 32) { use64 = 0; break; }
        *s_flag = use64;
    }
    __syncthreads();
    return *s_flag;
}

__device__ __forceinline__ int edge_at(const void* ei, int use64, size_t idx) {
    return use64 ? (int)((const long long*)ei)[idx]
                 : ((const int*)ei)[idx];
}

// ---------------------------------------------------------------------------
__global__ void k_degree(const void* __restrict__ ei) {
    __shared__ int s_flag;
    int use64 = detect_is64_block(ei, &s_flag);
    int tid = blockIdx.x * blockDim.x + threadIdx.x;
    int stride = gridDim.x * blockDim.x;
    for (int e = tid; e < N_EDGES; e += stride) {
        unsigned d = (unsigned)edge_at(ei, use64, (size_t)N_EDGES + e);
        if (d < N_NODES) atomicAdd(&g_deg[d], 1);
    }
}

// ---------------------------------------------------------------------------
__global__ __launch_bounds__(SCAN_BLK) void k_scanA() {
    __shared__ int warpsum[SCAN_BLK / 32];
    int t = threadIdx.x, b = blockIdx.x;
    int idx = b * SCAN_CHUNK + t * SCAN_ITEMS;
    int4 v = (idx < N_NODES + 4) ? ((const int4*)g_deg)[idx >> 2]
                                 : make_int4(0, 0, 0, 0);
    int s = 0;
    if (idx + 0 < N_NODES) s += v.x;
    if (idx + 1 < N_NODES) s += v.y;
    if (idx + 2 < N_NODES) s += v.z;
    if (idx + 3 < N_NODES) s += v.w;
#pragma unroll
    for (int o = 16; o > 0; o >>= 1) s += __shfl_down_sync(0xffffffffu, s, o);
    if ((t & 31) == 0) warpsum[t >> 5] = s;
    __syncthreads();
    if (t < SCAN_BLK / 32) {
        int ws = warpsum[t];
#pragma unroll
        for (int o = SCAN_BLK / 64; o > 0; o >>= 1)
            ws += __shfl_down_sync(0xffffffffu, ws, o);
        if (t == 0) g_bsum[b] = ws;
    }
}

// ---------------------------------------------------------------------------
__global__ __launch_bounds__(SCAN_BLK) void k_scanC() {
    __shared__ int sh[SCAN_BLK];
    __shared__ int s_base;
    int t = threadIdx.x, b = blockIdx.x;

    if (t < 32) {
        int v = 0;
        for (int i = t; i < b; i += 32) v += g_bsum[i];
#pragma unroll
        for (int o = 16; o > 0; o >>= 1) v += __shfl_down_sync(0xffffffffu, v, o);
        if (t == 0) s_base = v;
    }

    int idx = b * SCAN_CHUNK + t * SCAN_ITEMS;
    int4 v = (idx < N_NODES + 4) ? ((const int4*)g_deg)[idx >> 2]
                                 : make_int4(0, 0, 0, 0);
    if (idx < N_NODES + 4)
        ((int4*)g_deg)[idx >> 2] = make_int4(0, 0, 0, 0);
    int d0 = (idx + 0 < N_NODES) ? v.x : 0;
    int d1 = (idx + 1 < N_NODES) ? v.y : 0;
    int d2 = (idx + 2 < N_NODES) ? v.z : 0;
    int d3 = (idx + 3 < N_NODES) ? v.w : 0;
    sh[t] = d0 + d1 + d2 + d3;
    __syncthreads();
#pragma unroll
    for (int d = 1; d < SCAN_BLK; d <<= 1) {
        int u = (t >= d) ? sh[t - d] : 0;
        __syncthreads();
        sh[t] += u;
        __syncthreads();
    }
    int run = s_base + ((t > 0) ? sh[t - 1] : 0);
    int dg[4] = {d0, d1, d2, d3};
#pragma unroll
    for (int j = 0; j < 4; j++) {
        int i = idx + j;
        if (i < N_NODES) {
            g_off[i] = run;
            g_cursor[i] = run;
            g_dinv[i] = rsqrtf((float)(dg[j] + 1));
            run += dg[j];
        }
    }
    if (b == SCAN_NBLK - 1 && t == SCAN_BLK - 1) g_off[N_NODES] = run;
}

// ---------------------------------------------------------------------------
// K3 (fused): blocks [0,FILL_BLOCKS) fill CSR; the rest run gemm1.
// gemm1: R8-style smem x staging (one crossbar pass per tile) — the LDG
// broadcast variant saturated L1tex wavefronts and was slower.
// ---------------------------------------------------------------------------
__global__ __launch_bounds__(256) void k_work(const float* __restrict__ x,
                                              const float* __restrict__ Wc,
                                              const void* __restrict__ ei) {
    extern __shared__ float sm[];

    if (blockIdx.x < FILL_BLOCKS) {
        __shared__ int s_flag;
        int use64 = detect_is64_block(ei, &s_flag);
        int tid = blockIdx.x * blockDim.x + threadIdx.x;
        int stride = FILL_BLOCKS * blockDim.x;
        for (int e = tid; e < N_EDGES; e += stride) {
            unsigned s = (unsigned)edge_at(ei, use64, e);
            unsigned d = (unsigned)edge_at(ei, use64, (size_t)N_EDGES + e);
            if (d < N_NODES && s < N_NODES) {
                int pos = atomicAdd(&g_cursor[d], 1);
                g_csr_src[pos] = (int)s;
            }
        }
        return;
    }

    float* Ws = sm;                          // 16384 floats
    float* xt = sm + D * D;                  // 8 warps * 8 rows * 128
    int tid = threadIdx.x, warp = tid >> 5, lane = tid & 31;
    int bid = blockIdx.x - FILL_BLOCKS;

    for (int i = tid; i < D * D / 4; i += 256)
        ((float4*)Ws)[i] = ((const float4*)Wc)[i];
    __syncthreads();

    float* xw = xt + warp * (RT * D);
    const int ngroups = (N_NODES + RT - 1) / RT;
    const int wstride = GEMM_BLOCKS * 8;
    for (int g = bid * 8 + warp; g < ngroups; g += wstride) {
        int row0 = g * RT;
#pragma unroll
        for (int r = 0; r < RT; r++) {
            int row = row0 + r;
            float4 v = (row < N_NODES) ? ((const float4*)(x + (size_t)row * D))[lane]
                                       : make_float4(0.f, 0.f, 0.f, 0.f);
            ((float4*)(xw + r * D))[lane] = v;
        }
        __syncwarp();

        unsigned long long a0[RT], a1[RT];
#pragma unroll
        for (int r = 0; r < RT; r++) { a0[r] = 0ull; a1[r] = 0ull; }
#pragma unroll 4
        for (int k = 0; k < D; k++) {
            ulonglong2 w = ((const ulonglong2*)(Ws + k * D))[lane];
#pragma unroll
            for (int r = 0; r < RT; r++) {
                unsigned xi = __float_as_uint(xw[r * D + k]);
                unsigned long long xp;
                PACK_DUP(xp, xi);
                FMA_X2(a0[r], xp, w.x);
                FMA_X2(a1[r], xp, w.y);
            }
        }
#pragma unroll
        for (int r = 0; r < RT; r++) {
            int row = row0 + r;
            if (row < N_NODES) {
                unsigned si = __float_as_uint(g_dinv[row]);
                unsigned long long sp, o0, o1;
                PACK_DUP(sp, si);
                MUL_X2(o0, a0[r], sp);
                MUL_X2(o1, a1[r], sp);
                ((ulonglong2*)(g_z + (size_t)row * D))[lane] = make_ulonglong2(o0, o1);
            }
        }
        __syncwarp();
    }
}

// ---------------------------------------------------------------------------
// K5: 1024-thread blocks (32 warps/SM), RTF=4 rows per warp tile.
// Gather of z into smem h-tile (pipelined idx prefetch), epilogue
// out = h @ (I+Wt) + x @ (W0-Wt) with x via float4 LDG broadcasts.
// ---------------------------------------------------------------------------
__global__ __launch_bounds__(1024, 1) void k_final(const float* __restrict__ x,
                                                   const float* __restrict__ bc,
                                                   const float* __restrict__ W0,
                                                   const float* __restrict__ Wt,
                                                   float* __restrict__ out) {
    extern __shared__ float sm[];
    float* M1s = sm;                          // 16384
    float* M2s = sm + D * D;                  // 16384
    float* bcs = sm + 2 * D * D;              // 128
    float* ht  = bcs + D;                     // 32 warps * RTF * 128 = 16384
    int*   ibase = (int*)(ht + 32 * RTF * D); // 32 warps * 64 ints
    int tid = threadIdx.x, warp = tid >> 5, lane = tid & 31;

    for (int i = tid; i < D * D / 4; i += 1024) {
        float4 wt = ((const float4*)Wt)[i];
        float4 w0 = ((const float4*)W0)[i];
        int r = (i * 4) / D, c0 = (i * 4) % D;
        float m1v[4] = {wt.x, wt.y, wt.z, wt.w};
        int dd = r - c0;
        if (dd >= 0 && dd < 4) m1v[dd] += 1.0f;
        ((float4*)M1s)[i] = make_float4(m1v[0], m1v[1], m1v[2], m1v[3]);
        ((float4*)M2s)[i] = make_float4(w0.x - wt.x, w0.y - wt.y,
                                        w0.z - wt.z, w0.w - wt.w);
    }
    if (tid < D) bcs[tid] = bc[tid];
    __syncthreads();

    float* htw  = ht + warp * (RTF * D);
    int*   ibuf = ibase + warp * 64;          // two 32-entry halves

    const int ngroups = (N_NODES + RTF - 1) / RTF;
    const int wstride = gridDim.x * 32;
    for (int g = blockIdx.x * 32 + warp; g < ngroups; g += wstride) {
        int row0 = g * RTF;

        int off_l = 0;
        if (lane <= RTF) {
            int rr = row0 + lane;
            off_l = __ldg(&g_off[rr < N_NODES ? rr : N_NODES]);
        }
        int rowE[RTF + 1];
#pragma unroll
        for (int r = 0; r <= RTF; r++)
            rowE[r] = __shfl_sync(0xffffffffu, off_l, r);

        {
            int n0 = rowE[1] - rowE[0];
            if (lane < (n0 < 32 ? n0 : 32)) ibuf[lane] = __ldg(&g_csr_src[rowE[0] + lane]);
        }

        // ---- gather phase with one-row-ahead idx prefetch
#pragma unroll
        for (int r = 0; r < RTF; r++) {
            __syncwarp();
            int* cur = ibuf + ((r & 1) << 5);
            if (r + 1 < RTF) {
                int* nxt = ibuf + (((r + 1) & 1) << 5);
                int nn = rowE[r + 2] - rowE[r + 1];
                if (lane < (nn < 32 ? nn : 32))
                    nxt[lane] = __ldg(&g_csr_src[rowE[r + 1] + lane]);
            }

            int row = row0 + r;
            if (row >= N_NODES) {
                ((float4*)(htw + r * D))[lane] = make_float4(0.f, 0.f, 0.f, 0.f);
                continue;
            }
            size_t base = (size_t)row * D;
            float4 acc = ((const float4*)(g_z + base))[lane];
            int n = rowE[r + 1] - rowE[r];
            int m = n < 32 ? n : 32;
            int i = 0;
            for (; i + 7 < m; i += 8) {
                int s0 = cur[i];     int s1 = cur[i + 1];
                int s2 = cur[i + 2]; int s3 = cur[i + 3];
                int s4 = cur[i + 4]; int s5 = cur[i + 5];
                int s6 = cur[i + 6]; int s7 = cur[i + 7];
                float4 v0 = ((const float4*)(g_z + (size_t)s0 * D))[lane];
                float4 v1 = ((const float4*)(g_z + (size_t)s1 * D))[lane];
                float4 v2 = ((const float4*)(g_z + (size_t)s2 * D))[lane];
                float4 v3 = ((const float4*)(g_z + (size_t)s3 * D))[lane];
                float4 v4 = ((const float4*)(g_z + (size_t)s4 * D))[lane];
                float4 v5 = ((const float4*)(g_z + (size_t)s5 * D))[lane];
                float4 v6 = ((const float4*)(g_z + (size_t)s6 * D))[lane];
                float4 v7 = ((const float4*)(g_z + (size_t)s7 * D))[lane];
                acc.x += ((v0.x + v1.x) + (v2.x + v3.x)) + ((v4.x + v5.x) + (v6.x + v7.x));
                acc.y += ((v0.y + v1.y) + (v2.y + v3.y)) + ((v4.y + v5.y) + (v6.y + v7.y));
                acc.z += ((v0.z + v1.z) + (v2.z + v3.z)) + ((v4.z + v5.z) + (v6.z + v7.z));
                acc.w += ((v0.w + v1.w) + (v2.w + v3.w)) + ((v4.w + v5.w) + (v6.w + v7.w));
            }
            for (; i < m; i++) {
                int s0 = cur[i];
                float4 v0 = ((const float4*)(g_z + (size_t)s0 * D))[lane];
                acc.x += v0.x; acc.y += v0.y; acc.z += v0.z; acc.w += v0.w;
            }
            for (int e = rowE[r] + 32; e < rowE[r + 1]; e++) {
                int s0 = __ldg(&g_csr_src[e]);
                float4 v0 = ((const float4*)(g_z + (size_t)s0 * D))[lane];
                acc.x += v0.x; acc.y += v0.y; acc.z += v0.z; acc.w += v0.w;
            }

            float s = g_dinv[row];
            float4 b4 = ((const float4*)bcs)[lane];
            float4 h4;
            h4.x = s * acc.x + b4.x;
            h4.y = s * acc.y + b4.y;
            h4.z = s * acc.z + b4.z;
            h4.w = s * acc.w + b4.w;
            ((float4*)(htw + r * D))[lane] = h4;
        }
        __syncwarp();

        // ---- dual GEMM: o[r] = h[r] @ M1 + x[r] @ M2  (packed f32x2)
        unsigned long long o0[RTF], o1[RTF];
#pragma unroll
        for (int r = 0; r < RTF; r++) { o0[r] = 0ull; o1[r] = 0ull; }
#pragma unroll 2
        for (int j = 0; j < D / 4; j++) {
            float4 xv[RTF];
#pragma unroll
            for (int r = 0; r < RTF; r++) {
                int row = row0 + r;
                xv[r] = (row < N_NODES)
                      ? __ldg(&((const float4*)(x + (size_t)row * D))[j])
                      : make_float4(0.f, 0.f, 0.f, 0.f);
            }
#pragma unroll
            for (int kk = 0; kk < 4; kk++) {
                int k = 4 * j + kk;
                ulonglong2 m1 = ((const ulonglong2*)(M1s + k * D))[lane];
                ulonglong2 m2 = ((const ulonglong2*)(M2s + k * D))[lane];
#pragma unroll
                for (int r = 0; r < RTF; r++) {
                    unsigned hi_ = __float_as_uint(htw[r * D + k]);
                    unsigned xi_ = __float_as_uint(f4c(xv[r], kk));
                    unsigned long long hp, xp;
                    PACK_DUP(hp, hi_);
                    PACK_DUP(xp, xi_);
                    FMA_X2(o0[r], hp, m1.x);
                    FMA_X2(o1[r], hp, m1.y);
                    FMA_X2(o0[r], xp, m2.x);
                    FMA_X2(o1[r], xp, m2.y);
                }
            }
        }
#pragma unroll
        for (int r = 0; r < RTF; r++) {
            int row = row0 + r;
            if (row < N_NODES)
                ((ulonglong2*)(out + (size_t)row * D))[lane] = make_ulonglong2(o0[r], o1[r]);
        }
        __syncwarp();
    }
}

// ---------------------------------------------------------------------------
extern "C" void kernel_launch(void* const* d_in, const int* in_sizes, int n_in,
                              void* d_out, int out_size) {
    const float* x  = (const float*)d_in[0];
    const void*  ei = d_in[1];
    const float* Wc = (const float*)d_in[2];
    const float* bc = (const float*)d_in[3];
    const float* W0 = (const float*)d_in[4];
    const float* Wt = (const float*)d_in[5];

    {
        const float* fx = nullptr; const void* fei = nullptr;
        const float* fbc = nullptr;
        const float* w[3] = {nullptr, nullptr, nullptr}; int nw = 0;
        for (int i = 0; i < n_in; i++) {
            int sz = in_sizes[i];
            if (sz == N_NODES * D)                           fx  = (const float*)d_in[i];
            else if (sz == 2 * N_EDGES || sz == 4 * N_EDGES) fei = d_in[i];
            else if (sz == D)                                fbc = (const float*)d_in[i];
            else if (sz == D * D && nw < 3)                  w[nw++] = (const float*)d_in[i];
        }
        if (fx)  x  = fx;
        if (fei) ei = fei;
        if (fbc) bc = fbc;
        if (nw == 3) { Wc = w[0]; W0 = w[1]; Wt = w[2]; }
    }
    float* out = (float*)d_out;

    int smem_work  = (D * D + 8 * RT * D) * (int)sizeof(float);               // 98,304 B
    int smem_final = (2 * D * D + D + 32 * RTF * D) * (int)sizeof(float)
                     + 32 * 64 * (int)sizeof(int);                             // 205,312 B
    cudaFuncSetAttribute(k_work, cudaFuncAttributeMaxDynamicSharedMemorySize, smem_work);
    cudaFuncSetAttribute(k_final, cudaFuncAttributeMaxDynamicSharedMemorySize, smem_final);

    k_degree<<<512, 256>>>(ei);
    k_scanA<<<SCAN_NBLK, SCAN_BLK>>>();
    k_scanC<<<SCAN_NBLK, SCAN_BLK>>>();
    k_work<<<FILL_BLOCKS + GEMM_BLOCKS, 256, smem_work>>>(x, Wc, ei);
    k_final<<<148, 1024, smem_final>>>(x, bc, W0, Wt, out);
}